// round 3
// baseline (speedup 1.0000x reference)
#include <cuda_runtime.h>
#include <cstdint>

#define N_TOT 65536
#define GRP   512
#define PER   128
#define DIM   256
#define SEQL  1534
#define HID   512

// ---------------- scratch (device globals; no allocation allowed) ----------
__device__ float g_hats[N_TOT * DIM];          // 64 MiB
__device__ float g_HAts[GRP * DIM];
__device__ float g_seq [1536 * DIM];
__device__ float g_xb1 [1536 * 512];
__device__ float g_xb2 [1536 * 512];
__device__ float g_wcT0[3 * 256 * 256];
__device__ float g_wcT1[3 * 256 * 512];
__device__ float g_wcT2[3 * 512 * 512];
__device__ float g_wcT3[3 * 512 * 256];
__device__ float g_wd1T[256 * 512];
__device__ float g_wd3T[512 * 256];
__device__ float g_sHS [GRP * 768];
__device__ float g_GT  [GRP * 512];

// ---------------- weight transposes ----------------------------------------
// Wc[co][ci][j] -> WcT[j][ci][co]
__global__ void transpose_conv_w(const float* __restrict__ w, float* __restrict__ wT,
                                 int Cout, int Cin)
{
    int idx = blockIdx.x * 256 + threadIdx.x;
    int tot = Cout * Cin * 3;
    if (idx < tot) {
        int j  = idx % 3;
        int ci = (idx / 3) % Cin;
        int co = idx / (3 * Cin);
        wT[(j * Cin + ci) * Cout + co] = w[idx];
    }
}
// w[R][C] -> wT[C][R]
__global__ void transpose_mat(const float* __restrict__ w, float* __restrict__ wT,
                              int R, int C)
{
    int idx = blockIdx.x * 256 + threadIdx.x;
    if (idx < R * C) {
        int r = idx / C, c = idx % C;
        wT[c * R + r] = w[idx];
    }
}

#define FMA44(acc, a, b)                                                      \
    acc[0][0] += a.x * b.x; acc[0][1] += a.x * b.y; acc[0][2] += a.x * b.z; acc[0][3] += a.x * b.w; \
    acc[1][0] += a.y * b.x; acc[1][1] += a.y * b.y; acc[1][2] += a.y * b.z; acc[1][3] += a.y * b.w; \
    acc[2][0] += a.z * b.x; acc[2][1] += a.z * b.y; acc[2][2] += a.z * b.z; acc[2][3] += a.z * b.w; \
    acc[3][0] += a.w * b.x; acc[3][1] += a.w * b.y; acc[3][2] += a.w * b.z; acc[3][3] += a.w * b.w;

// ---------------- generic 64x64 tiled GEMM: C = [relu](A@B + bias) ---------
__global__ __launch_bounds__(256)
void gemm64(const float* __restrict__ A, const float* __restrict__ B,
            const float* __restrict__ bias, float* __restrict__ C,
            int M, int N, int K, int doRelu)
{
    __shared__ float As[16][64];
    __shared__ float Bs[16][64];
    int tid = threadIdx.x;
    int tx = tid & 15, ty = tid >> 4;
    int row0 = blockIdx.y * 64, col0 = blockIdx.x * 64;
    int ar = tid >> 2,  ak = (tid & 3) * 4;     // A: 64 rows x 16 k
    int bk = tid >> 4,  bn = (tid & 15) * 4;    // B: 16 k   x 64 n
    float acc[4][4] = {};

    for (int k0 = 0; k0 < K; k0 += 16) {
        int arow = row0 + ar;
        float4 av = (arow < M) ? *(const float4*)(A + (size_t)arow * K + k0 + ak)
                               : make_float4(0.f, 0.f, 0.f, 0.f);
        As[ak + 0][ar] = av.x; As[ak + 1][ar] = av.y;
        As[ak + 2][ar] = av.z; As[ak + 3][ar] = av.w;
        float4 bv = *(const float4*)(B + (size_t)(k0 + bk) * N + col0 + bn);
        *(float4*)&Bs[bk][bn] = bv;
        __syncthreads();
        #pragma unroll
        for (int k = 0; k < 16; k++) {
            float4 a = *(float4*)&As[k][ty * 4];
            float4 b = *(float4*)&Bs[k][tx * 4];
            FMA44(acc, a, b);
        }
        __syncthreads();
    }
    #pragma unroll
    for (int i = 0; i < 4; i++) {
        int row = row0 + ty * 4 + i;
        if (row >= M) continue;
        #pragma unroll
        for (int j = 0; j < 4; j++) {
            int col = col0 + tx * 4 + j;
            float v = acc[i][j] + bias[col];
            if (doRelu) v = fmaxf(v, 0.f);
            C[(size_t)row * N + col] = v;
        }
    }
}

// ---------------- per-group max + state_seq build ---------------------------
__global__ void seg_reduce(const float* __restrict__ hats, const float* __restrict__ nodes,
                           const int* __restrict__ act, float* __restrict__ HAts,
                           float* __restrict__ seq)
{
    int g = blockIdx.x;
    int c = threadIdx.x;
    const float* base = hats + (size_t)g * PER * DIM + c;
    float m = -3.4e38f;
    #pragma unroll 4
    for (int r = 0; r < PER; r++) m = fmaxf(m, base[(size_t)r * DIM]);
    HAts[g * DIM + c] = m;
    if (g < GRP - 1) {
        seq[(3 * g + 0) * DIM + c] = nodes[g * DIM + c];
        seq[(3 * g + 1) * DIM + c] = m;
        int a = act[g];
        seq[(3 * g + 2) * DIM + c] = hats[((size_t)g * PER + a) * DIM + c];
    } else {
        seq[(SEQL - 1) * DIM + c] = nodes[(GRP - 1) * DIM + c];
    }
}

// ---------------- TCN layer: y=relu(conv+b); out=relu(y + res) --------------
__global__ __launch_bounds__(256)
void tcn_layer(const float* __restrict__ x, const float* __restrict__ wT,
               const float* __restrict__ bias, const float* __restrict__ wdT,
               float* __restrict__ out, int Cin, int Cout, int dil)
{
    __shared__ float As[16][64];
    __shared__ float Bs[16][64];
    int tid = threadIdx.x;
    int tx = tid & 15, ty = tid >> 4;
    int row0 = blockIdx.y * 64, col0 = blockIdx.x * 64;
    int ar = tid >> 2,  ak = (tid & 3) * 4;
    int bk = tid >> 4,  bn = (tid & 15) * 4;
    float accY[4][4] = {};
    float accR[4][4] = {};
    int npass = wdT ? 4 : 3;

    for (int pass = 0; pass < npass; pass++) {
        int shift = (pass < 3) ? (2 - pass) * dil : 0;
        const float* B = (pass < 3) ? (wT + (size_t)pass * Cin * Cout) : wdT;
        int t   = row0 + ar - shift;
        bool okA = (row0 + ar < SEQL) && (t >= 0);
        const float* Arow = x + (size_t)t * Cin + ak;
        for (int k0 = 0; k0 < Cin; k0 += 16) {
            float4 av = okA ? *(const float4*)(Arow + k0) : make_float4(0.f, 0.f, 0.f, 0.f);
            As[ak + 0][ar] = av.x; As[ak + 1][ar] = av.y;
            As[ak + 2][ar] = av.z; As[ak + 3][ar] = av.w;
            float4 bv = *(const float4*)(B + (size_t)(k0 + bk) * Cout + col0 + bn);
            *(float4*)&Bs[bk][bn] = bv;
            __syncthreads();
            if (pass < 3) {
                #pragma unroll
                for (int k = 0; k < 16; k++) {
                    float4 a = *(float4*)&As[k][ty * 4];
                    float4 b = *(float4*)&Bs[k][tx * 4];
                    FMA44(accY, a, b);
                }
            } else {
                #pragma unroll
                for (int k = 0; k < 16; k++) {
                    float4 a = *(float4*)&As[k][ty * 4];
                    float4 b = *(float4*)&Bs[k][tx * 4];
                    FMA44(accR, a, b);
                }
            }
            __syncthreads();
        }
    }
    #pragma unroll
    for (int i = 0; i < 4; i++) {
        int trow = row0 + ty * 4 + i;
        if (trow >= SEQL) continue;
        #pragma unroll
        for (int j = 0; j < 4; j++) {
            int co = col0 + tx * 4 + j;
            float r = wdT ? accR[i][j] : x[(size_t)trow * Cin + co];  // identity: Cin==Cout
            float v = fmaxf(accY[i][j] + bias[co], 0.f) + r;
            out[(size_t)trow * Cout + co] = fmaxf(v, 0.f);
        }
    }
}

// ---------------- build state_HS = [query | hs | HAts] ----------------------
__global__ void build_sHS(const float* __restrict__ query, const float* __restrict__ xfin,
                          const float* __restrict__ HAts, float* __restrict__ sHS)
{
    int g = blockIdx.x, c = threadIdx.x;
    sHS[g * 768 +   0 + c] = query[g * DIM + c];
    sHS[g * 768 + 256 + c] = xfin[(size_t)(3 * g) * DIM + c];
    sHS[g * 768 + 512 + c] = HAts[g * DIM + c];
}

// ---------------- final fused: out = relu(hats@Wp1bot + GT[g]) @ Wp2 + bp2 --
// One block per group (128 rows). Loops 8 column tiles of 64, K=256.
__global__ __launch_bounds__(256)
void final_kernel(const float* __restrict__ hats, const float* __restrict__ Wp1bot,
                  const float* __restrict__ GT, const float* __restrict__ Wp2,
                  const float* __restrict__ bp2, float* __restrict__ out)
{
    __shared__ float As[16][128];
    __shared__ float Bs[16][64];
    __shared__ float sGT[512];
    __shared__ float sW2[512];
    __shared__ float red[128][17];

    int g   = blockIdx.x;
    int tid = threadIdx.x;
    int tx = tid & 15, ty = tid >> 4;
    for (int i = tid; i < 512; i += 256) { sGT[i] = GT[g * 512 + i]; sW2[i] = Wp2[i]; }

    const float* Ablk = hats + (size_t)g * PER * DIM;
    int r  = tid >> 1;
    int kk = (tid & 1) * 8;
    int bk = tid >> 4, bn = (tid & 15) * 4;

    float qsum[8] = {};
    for (int ct = 0; ct < 8; ct++) {
        int col0 = ct * 64;
        float acc[8][4] = {};
        #pragma unroll
        for (int k0 = 0; k0 < 256; k0 += 16) {
            float4 a0 = *(const float4*)(Ablk + (size_t)r * DIM + k0 + kk);
            float4 a1 = *(const float4*)(Ablk + (size_t)r * DIM + k0 + kk + 4);
            As[kk + 0][r] = a0.x; As[kk + 1][r] = a0.y; As[kk + 2][r] = a0.z; As[kk + 3][r] = a0.w;
            As[kk + 4][r] = a1.x; As[kk + 5][r] = a1.y; As[kk + 6][r] = a1.z; As[kk + 7][r] = a1.w;
            float4 bv = *(const float4*)(Wp1bot + (size_t)(k0 + bk) * HID + col0 + bn);
            *(float4*)&Bs[bk][bn] = bv;
            __syncthreads();
            #pragma unroll
            for (int k = 0; k < 16; k++) {
                float4 b = *(float4*)&Bs[k][tx * 4];
                #pragma unroll
                for (int i = 0; i < 8; i++) {
                    float a = As[k][ty * 8 + i];
                    acc[i][0] += a * b.x; acc[i][1] += a * b.y;
                    acc[i][2] += a * b.z; acc[i][3] += a * b.w;
                }
            }
            __syncthreads();
        }
        #pragma unroll
        for (int i = 0; i < 8; i++) {
            #pragma unroll
            for (int j = 0; j < 4; j++) {
                int co = col0 + tx * 4 + j;
                float h = fmaxf(acc[i][j] + sGT[co], 0.f);
                qsum[i] += h * sW2[co];
            }
        }
    }
    #pragma unroll
    for (int i = 0; i < 8; i++) red[ty * 8 + i][tx] = qsum[i];
    __syncthreads();
    if (tid < 128) {
        float s = 0.f;
        #pragma unroll
        for (int t = 0; t < 16; t++) s += red[tid][t];
        out[(size_t)g * PER + tid] = s + bp2[0];
    }
}

// ---------------- launcher --------------------------------------------------
extern "C" void kernel_launch(void* const* d_in, const int* in_sizes, int n_in,
                              void* d_out, int out_size)
{
    const float* NEs   = (const float*)d_in[0];
    const float* nodes = (const float*)d_in[1];
    const float* query = (const float*)d_in[2];
    /* d_in[3] num_neighbors: constant PER=128 by construction */
    const int*   act   = (const int*)d_in[4];
    const float* Wa    = (const float*)d_in[5];
    const float* ba    = (const float*)d_in[6];
    const float* Wc0   = (const float*)d_in[7];
    const float* bc0   = (const float*)d_in[8];
    const float* Wc1   = (const float*)d_in[9];
    const float* bc1   = (const float*)d_in[10];
    const float* Wd1   = (const float*)d_in[11];
    const float* Wc2   = (const float*)d_in[12];
    const float* bc2   = (const float*)d_in[13];
    const float* Wc3   = (const float*)d_in[14];
    const float* bc3   = (const float*)d_in[15];
    const float* Wd3   = (const float*)d_in[16];
    const float* Wp1   = (const float*)d_in[17];
    const float* bp1   = (const float*)d_in[18];
    const float* Wp2   = (const float*)d_in[19];
    const float* bp2   = (const float*)d_in[20];
    float* out = (float*)d_out;

    float *hats, *HAts, *seq, *xb1, *xb2;
    float *wcT0, *wcT1, *wcT2, *wcT3, *wd1T, *wd3T, *sHS, *GT;
    cudaGetSymbolAddress((void**)&hats, g_hats);
    cudaGetSymbolAddress((void**)&HAts, g_HAts);
    cudaGetSymbolAddress((void**)&seq,  g_seq);
    cudaGetSymbolAddress((void**)&xb1,  g_xb1);
    cudaGetSymbolAddress((void**)&xb2,  g_xb2);
    cudaGetSymbolAddress((void**)&wcT0, g_wcT0);
    cudaGetSymbolAddress((void**)&wcT1, g_wcT1);
    cudaGetSymbolAddress((void**)&wcT2, g_wcT2);
    cudaGetSymbolAddress((void**)&wcT3, g_wcT3);
    cudaGetSymbolAddress((void**)&wd1T, g_wd1T);
    cudaGetSymbolAddress((void**)&wd3T, g_wd3T);
    cudaGetSymbolAddress((void**)&sHS,  g_sHS);
    cudaGetSymbolAddress((void**)&GT,   g_GT);

    // weight prep (tiny)
    transpose_conv_w<<<(256 * 256 * 3 + 255) / 256, 256>>>(Wc0, wcT0, 256, 256);
    transpose_conv_w<<<(512 * 256 * 3 + 255) / 256, 256>>>(Wc1, wcT1, 512, 256);
    transpose_conv_w<<<(512 * 512 * 3 + 255) / 256, 256>>>(Wc2, wcT2, 512, 512);
    transpose_conv_w<<<(256 * 512 * 3 + 255) / 256, 256>>>(Wc3, wcT3, 256, 512);
    transpose_mat<<<(512 * 256 + 255) / 256, 256>>>(Wd1, wd1T, 512, 256);
    transpose_mat<<<(256 * 512 + 255) / 256, 256>>>(Wd3, wd3T, 256, 512);

    // 1) hats = relu(NEs @ Wa + ba)
    gemm64<<<dim3(DIM / 64, N_TOT / 64), 256>>>(NEs, Wa, ba, hats, N_TOT, DIM, DIM, 1);

    // 2) segment max + select + state_seq
    seg_reduce<<<GRP, DIM>>>(hats, nodes, act, HAts, seq);

    // 3) TCN (seq-major [L, C])
    tcn_layer<<<dim3(4, 24), 256>>>(seq, wcT0, bc0, nullptr, xb1, 256, 256, 1);
    tcn_layer<<<dim3(8, 24), 256>>>(xb1, wcT1, bc1, wd1T,    xb2, 256, 512, 2);
    tcn_layer<<<dim3(8, 24), 256>>>(xb2, wcT2, bc2, nullptr, xb1, 512, 512, 4);
    tcn_layer<<<dim3(4, 24), 256>>>(xb1, wcT3, bc3, wd3T,    xb2, 512, 256, 8);

    // 4) state_HS and group term = state_HS @ Wp1[0:768] + bp1
    build_sHS<<<GRP, DIM>>>(query, xb2, HAts, sHS);
    gemm64<<<dim3(HID / 64, GRP / 64), 256>>>(sHS, Wp1, bp1, GT, GRP, HID, 768, 0);

    // 5) fused final GEMM + Wp2 reduction
    final_kernel<<<GRP, 256>>>(hats, Wp1 + 768 * HID, GT, Wp2, bp2, out);
}

// round 4
// speedup vs baseline: 1.1080x; 1.1080x over previous
#include <cuda_runtime.h>
#include <cuda_bf16.h>
#include <cstdint>

#define N_TOT 65536
#define GRP   512
#define PER   128
#define DIM   256
#define SEQL  1534
#define HID   512

typedef __nv_bfloat16 bf16;

// ---------------- scratch (device globals; no allocation allowed) ----------
__device__ bf16  g_NEh [N_TOT * DIM];
__device__ bf16  g_NEl [N_TOT * DIM];
__device__ float g_hats[N_TOT * DIM];
__device__ bf16  g_hh  [N_TOT * DIM];
__device__ bf16  g_hl  [N_TOT * DIM];
__device__ float g_HAts[GRP * DIM];
__device__ float g_seqf[1536 * DIM];
__device__ bf16  g_seqh[1536 * DIM];
__device__ bf16  g_seql[1536 * DIM];
__device__ float g_x1f [1536 * 512];
__device__ bf16  g_x1h [1536 * 512];
__device__ bf16  g_x1l [1536 * 512];
__device__ float g_x2f [1536 * 512];
__device__ bf16  g_x2h [1536 * 512];
__device__ bf16  g_x2l [1536 * 512];
__device__ float g_resf[1536 * 512];
__device__ bf16  g_wah [DIM * DIM];
__device__ bf16  g_wal [DIM * DIM];
__device__ bf16  g_wc0h[3 * 256 * 256];
__device__ bf16  g_wc0l[3 * 256 * 256];
__device__ bf16  g_wc1h[3 * 512 * 256];
__device__ bf16  g_wc1l[3 * 512 * 256];
__device__ bf16  g_wc2h[3 * 512 * 512];
__device__ bf16  g_wc2l[3 * 512 * 512];
__device__ bf16  g_wc3h[3 * 256 * 512];
__device__ bf16  g_wc3l[3 * 256 * 512];
__device__ bf16  g_wd1h[512 * 256];
__device__ bf16  g_wd1l[512 * 256];
__device__ bf16  g_wd3h[256 * 512];
__device__ bf16  g_wd3l[256 * 512];
__device__ bf16  g_wp1th[512 * 768];
__device__ bf16  g_wp1tl[512 * 768];
__device__ bf16  g_wp1bh[512 * 256];
__device__ bf16  g_wp1bl[512 * 256];
__device__ bf16  g_sHSh[GRP * 768];
__device__ bf16  g_sHSl[GRP * 768];
__device__ float g_GT  [GRP * 512];

// ---------------- split helpers --------------------------------------------
__device__ __forceinline__ void split2(float v, bf16& h, bf16& l) {
    h = __float2bfloat16(v);
    l = __float2bfloat16(v - __bfloat162float(h));
}

// in fp32 [n] -> hi/lo bf16 [n] (same layout)
__global__ void split_arr(const float* __restrict__ x, bf16* __restrict__ h,
                          bf16* __restrict__ l, int n)
{
    int i = blockIdx.x * 256 + threadIdx.x;
    if (i < n) { bf16 a, b; split2(x[i], a, b); h[i] = a; l[i] = b; }
}

// w[K][N] row-major -> hi/lo [N][K]
__global__ void tsplit(const float* __restrict__ w, bf16* __restrict__ h,
                       bf16* __restrict__ l, int K, int N)
{
    int i = blockIdx.x * 256 + threadIdx.x;
    if (i < K * N) {
        int k = i / N, n = i % N;
        bf16 a, b; split2(w[i], a, b);
        h[(size_t)n * K + k] = a;
        l[(size_t)n * K + k] = b;
    }
}

// Wc[co][ci][j] -> [j][co][ci] hi/lo
__global__ void split_conv(const float* __restrict__ w, bf16* __restrict__ h,
                           bf16* __restrict__ l, int Cout, int Cin)
{
    int i = blockIdx.x * 256 + threadIdx.x;
    if (i < Cout * Cin * 3) {
        int j  = i % 3;
        int ci = (i / 3) % Cin;
        int co = i / (3 * Cin);
        bf16 a, b; split2(w[i], a, b);
        size_t d = ((size_t)j * Cout + co) * Cin + ci;
        h[d] = a; l[d] = b;
    }
}

// ---------------- MMA core --------------------------------------------------
__device__ __forceinline__ void mma_bf16(float* c, const uint32_t* a, const uint32_t* b) {
    asm volatile(
        "mma.sync.aligned.m16n8k16.row.col.f32.bf16.bf16.f32 "
        "{%0,%1,%2,%3}, {%4,%5,%6,%7}, {%8,%9}, {%0,%1,%2,%3};\n"
        : "+f"(c[0]), "+f"(c[1]), "+f"(c[2]), "+f"(c[3])
        : "r"(a[0]), "r"(a[1]), "r"(a[2]), "r"(a[3]), "r"(b[0]), "r"(b[1]));
}

#define ST8(S, lr, cb, swz, v0, v1)                                            \
    S[lr][((cb) + 0) ^ (swz)] = v0.x; S[lr][((cb) + 1) ^ (swz)] = v0.y;        \
    S[lr][((cb) + 2) ^ (swz)] = v0.z; S[lr][((cb) + 3) ^ (swz)] = v0.w;        \
    S[lr][((cb) + 4) ^ (swz)] = v1.x; S[lr][((cb) + 5) ^ (swz)] = v1.y;        \
    S[lr][((cb) + 6) ^ (swz)] = v1.z; S[lr][((cb) + 7) ^ (swz)] = v1.w;

// one k=32 chunk of a 64x32 warp tile; smem tiles are [128][16] u32, swizzled
__device__ __forceinline__ void warp_tile_k32(
    const uint32_t (*Ah)[16], const uint32_t (*Al)[16],
    const uint32_t (*Bh)[16], const uint32_t (*Bl)[16],
    int wm, int wn, int lane, float acc[4][4][4])
{
    #pragma unroll
    for (int ks = 0; ks < 2; ks++) {
        int c0 = ks * 8 + (lane & 3);
        int c1 = c0 + 4;
        uint32_t ah[4][4], al[4][4];
        #pragma unroll
        for (int mt = 0; mt < 4; mt++) {
            int r   = wm + mt * 16 + (lane >> 2);
            int swz = (r & 7) << 1;
            ah[mt][0] = Ah[r][c0 ^ swz];   ah[mt][1] = Ah[r + 8][c0 ^ swz];
            ah[mt][2] = Ah[r][c1 ^ swz];   ah[mt][3] = Ah[r + 8][c1 ^ swz];
            al[mt][0] = Al[r][c0 ^ swz];   al[mt][1] = Al[r + 8][c0 ^ swz];
            al[mt][2] = Al[r][c1 ^ swz];   al[mt][3] = Al[r + 8][c1 ^ swz];
        }
        #pragma unroll
        for (int nt = 0; nt < 4; nt++) {
            int n   = wn + nt * 8 + (lane >> 2);
            int swz = (n & 7) << 1;
            uint32_t bh[2], bl[2];
            bh[0] = Bh[n][c0 ^ swz];  bh[1] = Bh[n][c1 ^ swz];
            bl[0] = Bl[n][c0 ^ swz];  bl[1] = Bl[n][c1 ^ swz];
            #pragma unroll
            for (int mt = 0; mt < 4; mt++) {
                mma_bf16(acc[mt][nt], ah[mt], bh);
                mma_bf16(acc[mt][nt], ah[mt], bl);
                mma_bf16(acc[mt][nt], al[mt], bh);
            }
        }
    }
}

// ---------------- generic bf16x3 GEMM: C = [relu](A@B^T_layout + bias) ------
// A: [M][K] hi/lo bf16; B: [N][K] hi/lo bf16 (i.e. weights pre-transposed)
// grid (N/128, M/128), 256 threads.
__global__ __launch_bounds__(256, 1)
void mma_gemm(const bf16* __restrict__ Ahg, const bf16* __restrict__ Alg,
              const bf16* __restrict__ Bhg, const bf16* __restrict__ Blg,
              const float* __restrict__ bias, float* __restrict__ Cf,
              bf16* __restrict__ Ch, bf16* __restrict__ Cl,
              int M, int N, int K, int doRelu)
{
    __shared__ uint32_t Ash[128][16], Asl[128][16], Bsh[128][16], Bsl[128][16];
    int tid = threadIdx.x, lane = tid & 31, w = tid >> 5;
    int wm = (w & 1) * 64, wn = (w >> 1) * 32;
    int row0 = blockIdx.y * 128, col0 = blockIdx.x * 128;
    int lr = tid >> 1, hf = tid & 1, cb = hf * 8, swz = (lr & 7) << 1;
    float acc[4][4][4] = {};

    for (int k0 = 0; k0 < K; k0 += 32) {
        const uint32_t* pa = (const uint32_t*)(Ahg + (size_t)(row0 + lr) * K + k0) + cb;
        const uint32_t* pl = (const uint32_t*)(Alg + (size_t)(row0 + lr) * K + k0) + cb;
        const uint32_t* pb = (const uint32_t*)(Bhg + (size_t)(col0 + lr) * K + k0) + cb;
        const uint32_t* pm = (const uint32_t*)(Blg + (size_t)(col0 + lr) * K + k0) + cb;
        uint4 a0 = *(const uint4*)pa, a1 = *(const uint4*)(pa + 4);
        uint4 a2 = *(const uint4*)pl, a3 = *(const uint4*)(pl + 4);
        uint4 b0 = *(const uint4*)pb, b1 = *(const uint4*)(pb + 4);
        uint4 b2 = *(const uint4*)pm, b3 = *(const uint4*)(pm + 4);
        __syncthreads();
        ST8(Ash, lr, cb, swz, a0, a1);
        ST8(Asl, lr, cb, swz, a2, a3);
        ST8(Bsh, lr, cb, swz, b0, b1);
        ST8(Bsl, lr, cb, swz, b2, b3);
        __syncthreads();
        warp_tile_k32(Ash, Asl, Bsh, Bsl, wm, wn, lane, acc);
    }

    #pragma unroll
    for (int mt = 0; mt < 4; mt++) {
        #pragma unroll
        for (int nt = 0; nt < 4; nt++) {
            #pragma unroll
            for (int i = 0; i < 4; i++) {
                int rr = row0 + wm + mt * 16 + (lane >> 2) + (i >> 1) * 8;
                int cc = col0 + wn + nt * 8 + (lane & 3) * 2 + (i & 1);
                float v = acc[mt][nt][i];
                if (bias) v += bias[cc];
                if (doRelu) v = fmaxf(v, 0.f);
                size_t idx = (size_t)rr * N + cc;
                if (Cf) Cf[idx] = v;
                if (Ch) { bf16 a, b; split2(v, a, b); Ch[idx] = a; Cl[idx] = b; }
            }
        }
    }
}

// ---------------- per-group max + state_seq build ---------------------------
__global__ void seg_reduce(const float* __restrict__ hats, const float* __restrict__ nodes,
                           const int* __restrict__ act, float* __restrict__ HAts,
                           float* __restrict__ seqf, bf16* __restrict__ seqh,
                           bf16* __restrict__ seql)
{
    int g = blockIdx.x;
    int c = threadIdx.x;
    const float* base = hats + (size_t)g * PER * DIM + c;
    float m = -3.4e38f;
    #pragma unroll 4
    for (int r = 0; r < PER; r++) m = fmaxf(m, base[(size_t)r * DIM]);
    HAts[g * DIM + c] = m;
    auto wr = [&](int row, float v) {
        size_t id = (size_t)row * DIM + c;
        seqf[id] = v;
        bf16 a, b; split2(v, a, b);
        seqh[id] = a; seql[id] = b;
    };
    if (g < GRP - 1) {
        wr(3 * g + 0, nodes[g * DIM + c]);
        wr(3 * g + 1, m);
        int a = act[g];
        wr(3 * g + 2, hats[((size_t)g * PER + a) * DIM + c]);
    } else {
        wr(SEQL - 1, nodes[(GRP - 1) * DIM + c]);
    }
}

// ---------------- TCN layer via 3 shifted MMA passes ------------------------
// out = relu( relu(conv(x)+bias) + Rf )   (Rf = x itself for identity layers,
// or the precomputed x@Wd residual). grid (Cout/128, 12).
__global__ __launch_bounds__(256, 1)
void tcn_mma(const bf16* __restrict__ Xh, const bf16* __restrict__ Xl,
             const bf16* __restrict__ Wh, const bf16* __restrict__ Wl,
             const float* __restrict__ bias, const float* __restrict__ Rf,
             float* __restrict__ Of, bf16* __restrict__ Oh, bf16* __restrict__ Ol,
             int Cin, int Cout, int dil)
{
    __shared__ uint32_t Ash[128][16], Asl[128][16], Bsh[128][16], Bsl[128][16];
    int tid = threadIdx.x, lane = tid & 31, w = tid >> 5;
    int wm = (w & 1) * 64, wn = (w >> 1) * 32;
    int row0 = blockIdx.y * 128, col0 = blockIdx.x * 128;
    int lr = tid >> 1, hf = tid & 1, cb = hf * 8, swz = (lr & 7) << 1;
    float acc[4][4][4] = {};
    uint4 z = make_uint4(0u, 0u, 0u, 0u);

    for (int p = 0; p < 3; p++) {
        int shift = (2 - p) * dil;
        int t = row0 + lr - shift;
        bool ok = (t >= 0);
        const bf16* Bhg = Wh + (size_t)p * Cout * Cin;
        const bf16* Blg = Wl + (size_t)p * Cout * Cin;
        for (int k0 = 0; k0 < Cin; k0 += 32) {
            const uint32_t* pa = (const uint32_t*)(Xh + (size_t)t * Cin + k0) + cb;
            const uint32_t* pl = (const uint32_t*)(Xl + (size_t)t * Cin + k0) + cb;
            uint4 a0 = ok ? *(const uint4*)pa : z;
            uint4 a1 = ok ? *(const uint4*)(pa + 4) : z;
            uint4 a2 = ok ? *(const uint4*)pl : z;
            uint4 a3 = ok ? *(const uint4*)(pl + 4) : z;
            const uint32_t* pb = (const uint32_t*)(Bhg + (size_t)(col0 + lr) * Cin + k0) + cb;
            const uint32_t* pm = (const uint32_t*)(Blg + (size_t)(col0 + lr) * Cin + k0) + cb;
            uint4 b0 = *(const uint4*)pb, b1 = *(const uint4*)(pb + 4);
            uint4 b2 = *(const uint4*)pm, b3 = *(const uint4*)(pm + 4);
            __syncthreads();
            ST8(Ash, lr, cb, swz, a0, a1);
            ST8(Asl, lr, cb, swz, a2, a3);
            ST8(Bsh, lr, cb, swz, b0, b1);
            ST8(Bsl, lr, cb, swz, b2, b3);
            __syncthreads();
            warp_tile_k32(Ash, Asl, Bsh, Bsl, wm, wn, lane, acc);
        }
    }

    #pragma unroll
    for (int mt = 0; mt < 4; mt++) {
        #pragma unroll
        for (int nt = 0; nt < 4; nt++) {
            #pragma unroll
            for (int i = 0; i < 4; i++) {
                int rr = row0 + wm + mt * 16 + (lane >> 2) + (i >> 1) * 8;
                int cc = col0 + wn + nt * 8 + (lane & 3) * 2 + (i & 1);
                if (rr >= SEQL) continue;
                size_t idx = (size_t)rr * Cout + cc;
                float v = fmaxf(acc[mt][nt][i] + bias[cc], 0.f) + Rf[idx];
                v = fmaxf(v, 0.f);
                Of[idx] = v;
                bf16 a, b; split2(v, a, b);
                Oh[idx] = a; Ol[idx] = b;
            }
        }
    }
}

// ---------------- build state_HS = [query | hs | HAts] (hi/lo) --------------
__global__ void build_sHS(const float* __restrict__ query, const float* __restrict__ xf,
                          const float* __restrict__ HAts, bf16* __restrict__ h,
                          bf16* __restrict__ l)
{
    int g = blockIdx.x, c = threadIdx.x;
    bf16 a, b;
    split2(query[g * DIM + c], a, b);
    h[g * 768 + c] = a; l[g * 768 + c] = b;
    split2(xf[(size_t)(3 * g) * DIM + c], a, b);
    h[g * 768 + 256 + c] = a; l[g * 768 + 256 + c] = b;
    split2(HAts[g * DIM + c], a, b);
    h[g * 768 + 512 + c] = a; l[g * 768 + 512 + c] = b;
}

// ---------------- final fused: out = relu(hats@Wp1bot + GT[g]) @ Wp2 + bp2 --
// One block per group: A = hats rows [g*128, g*128+128), K=256;
// B = Wp1bot^T [512][256]; loop 4 n-chunks of 128.
__global__ __launch_bounds__(256, 1)
void final_mma(const bf16* __restrict__ Hh, const bf16* __restrict__ Hl,
               const bf16* __restrict__ Bhg, const bf16* __restrict__ Blg,
               const float* __restrict__ GT, const float* __restrict__ W2,
               const float* __restrict__ bp2, float* __restrict__ out)
{
    __shared__ uint32_t Ash[128][16], Asl[128][16], Bsh[128][16], Bsl[128][16];
    __shared__ float sGT[512], sW2[512];
    __shared__ float red[128][4];

    int g = blockIdx.x;
    int tid = threadIdx.x, lane = tid & 31, w = tid >> 5;
    int wm = (w & 1) * 64, wn = (w >> 1) * 32;
    int lr = tid >> 1, hf = tid & 1, cb = hf * 8, swz = (lr & 7) << 1;

    for (int i = tid; i < 512; i += 256) { sGT[i] = GT[(size_t)g * 512 + i]; sW2[i] = W2[i]; }

    const bf16* Ahg = Hh + (size_t)g * PER * DIM;
    const bf16* Alg = Hl + (size_t)g * PER * DIM;
    float qrow[8] = {};

    for (int nc = 0; nc < 4; nc++) {
        int col0 = nc * 128;
        float acc[4][4][4] = {};
        for (int k0 = 0; k0 < 256; k0 += 32) {
            const uint32_t* pa = (const uint32_t*)(Ahg + (size_t)lr * DIM + k0) + cb;
            const uint32_t* pl = (const uint32_t*)(Alg + (size_t)lr * DIM + k0) + cb;
            const uint32_t* pb = (const uint32_t*)(Bhg + (size_t)(col0 + lr) * DIM + k0) + cb;
            const uint32_t* pm = (const uint32_t*)(Blg + (size_t)(col0 + lr) * DIM + k0) + cb;
            uint4 a0 = *(const uint4*)pa, a1 = *(const uint4*)(pa + 4);
            uint4 a2 = *(const uint4*)pl, a3 = *(const uint4*)(pl + 4);
            uint4 b0 = *(const uint4*)pb, b1 = *(const uint4*)(pb + 4);
            uint4 b2 = *(const uint4*)pm, b3 = *(const uint4*)(pm + 4);
            __syncthreads();
            ST8(Ash, lr, cb, swz, a0, a1);
            ST8(Asl, lr, cb, swz, a2, a3);
            ST8(Bsh, lr, cb, swz, b0, b1);
            ST8(Bsl, lr, cb, swz, b2, b3);
            __syncthreads();
            warp_tile_k32(Ash, Asl, Bsh, Bsl, wm, wn, lane, acc);
        }
        #pragma unroll
        for (int mt = 0; mt < 4; mt++) {
            #pragma unroll
            for (int nt = 0; nt < 4; nt++) {
                #pragma unroll
                for (int i = 0; i < 4; i++) {
                    int cc = col0 + wn + nt * 8 + (lane & 3) * 2 + (i & 1);
                    float hv = fmaxf(acc[mt][nt][i] + sGT[cc], 0.f);
                    qrow[mt * 2 + (i >> 1)] += hv * sW2[cc];
                }
            }
        }
    }

    #pragma unroll
    for (int j = 0; j < 8; j++) {
        float v = qrow[j];
        v += __shfl_xor_sync(0xffffffffu, v, 1);
        v += __shfl_xor_sync(0xffffffffu, v, 2);
        int r = wm + (j >> 1) * 16 + (j & 1) * 8 + (lane >> 2);
        if ((lane & 3) == 0) red[r][w >> 1] = v;
    }
    __syncthreads();
    if (tid < 128)
        out[(size_t)g * PER + tid] = red[tid][0] + red[tid][1] + red[tid][2] + red[tid][3] + bp2[0];
}

// ---------------- launcher --------------------------------------------------
extern "C" void kernel_launch(void* const* d_in, const int* in_sizes, int n_in,
                              void* d_out, int out_size)
{
    const float* NEs   = (const float*)d_in[0];
    const float* nodes = (const float*)d_in[1];
    const float* query = (const float*)d_in[2];
    const int*   act   = (const int*)d_in[4];
    const float* Wa    = (const float*)d_in[5];
    const float* ba    = (const float*)d_in[6];
    const float* Wc0   = (const float*)d_in[7];
    const float* bc0   = (const float*)d_in[8];
    const float* Wc1   = (const float*)d_in[9];
    const float* bc1   = (const float*)d_in[10];
    const float* Wd1   = (const float*)d_in[11];
    const float* Wc2   = (const float*)d_in[12];
    const float* bc2   = (const float*)d_in[13];
    const float* Wc3   = (const float*)d_in[14];
    const float* bc3   = (const float*)d_in[15];
    const float* Wd3   = (const float*)d_in[16];
    const float* Wp1   = (const float*)d_in[17];
    const float* bp1   = (const float*)d_in[18];
    const float* Wp2   = (const float*)d_in[19];
    const float* bp2   = (const float*)d_in[20];
    float* out = (float*)d_out;

    bf16 *NEh, *NEl, *hh, *hl, *seqh, *seql, *x1h, *x1l, *x2h, *x2l;
    bf16 *wah, *wal, *wc0h, *wc0l, *wc1h, *wc1l, *wc2h, *wc2l, *wc3h, *wc3l;
    bf16 *wd1h, *wd1l, *wd3h, *wd3l, *wp1th, *wp1tl, *wp1bh, *wp1bl, *sHSh, *sHSl;
    float *hats, *HAts, *seqf, *x1f, *x2f, *resf, *GT;
    cudaGetSymbolAddress((void**)&NEh,  g_NEh);   cudaGetSymbolAddress((void**)&NEl,  g_NEl);
    cudaGetSymbolAddress((void**)&hats, g_hats);
    cudaGetSymbolAddress((void**)&hh,   g_hh);    cudaGetSymbolAddress((void**)&hl,   g_hl);
    cudaGetSymbolAddress((void**)&HAts, g_HAts);
    cudaGetSymbolAddress((void**)&seqf, g_seqf);
    cudaGetSymbolAddress((void**)&seqh, g_seqh);  cudaGetSymbolAddress((void**)&seql, g_seql);
    cudaGetSymbolAddress((void**)&x1f,  g_x1f);
    cudaGetSymbolAddress((void**)&x1h,  g_x1h);   cudaGetSymbolAddress((void**)&x1l,  g_x1l);
    cudaGetSymbolAddress((void**)&x2f,  g_x2f);
    cudaGetSymbolAddress((void**)&x2h,  g_x2h);   cudaGetSymbolAddress((void**)&x2l,  g_x2l);
    cudaGetSymbolAddress((void**)&resf, g_resf);
    cudaGetSymbolAddress((void**)&wah,  g_wah);   cudaGetSymbolAddress((void**)&wal,  g_wal);
    cudaGetSymbolAddress((void**)&wc0h, g_wc0h);  cudaGetSymbolAddress((void**)&wc0l, g_wc0l);
    cudaGetSymbolAddress((void**)&wc1h, g_wc1h);  cudaGetSymbolAddress((void**)&wc1l, g_wc1l);
    cudaGetSymbolAddress((void**)&wc2h, g_wc2h);  cudaGetSymbolAddress((void**)&wc2l, g_wc2l);
    cudaGetSymbolAddress((void**)&wc3h, g_wc3h);  cudaGetSymbolAddress((void**)&wc3l, g_wc3l);
    cudaGetSymbolAddress((void**)&wd1h, g_wd1h);  cudaGetSymbolAddress((void**)&wd1l, g_wd1l);
    cudaGetSymbolAddress((void**)&wd3h, g_wd3h);  cudaGetSymbolAddress((void**)&wd3l, g_wd3l);
    cudaGetSymbolAddress((void**)&wp1th, g_wp1th); cudaGetSymbolAddress((void**)&wp1tl, g_wp1tl);
    cudaGetSymbolAddress((void**)&wp1bh, g_wp1bh); cudaGetSymbolAddress((void**)&wp1bl, g_wp1bl);
    cudaGetSymbolAddress((void**)&sHSh, g_sHSh);  cudaGetSymbolAddress((void**)&sHSl, g_sHSl);
    cudaGetSymbolAddress((void**)&GT,   g_GT);

    // ---- operand prep (split / transpose-split) ----
    split_arr<<<(N_TOT * DIM + 255) / 256, 256>>>(NEs, NEh, NEl, N_TOT * DIM);
    tsplit<<<(256 * 256 + 255) / 256, 256>>>(Wa, wah, wal, 256, 256);
    split_conv<<<(256 * 256 * 3 + 255) / 256, 256>>>(Wc0, wc0h, wc0l, 256, 256);
    split_conv<<<(512 * 256 * 3 + 255) / 256, 256>>>(Wc1, wc1h, wc1l, 512, 256);
    split_conv<<<(512 * 512 * 3 + 255) / 256, 256>>>(Wc2, wc2h, wc2l, 512, 512);
    split_conv<<<(256 * 512 * 3 + 255) / 256, 256>>>(Wc3, wc3h, wc3l, 256, 512);
    split_arr<<<(512 * 256 + 255) / 256, 256>>>(Wd1, wd1h, wd1l, 512 * 256);
    split_arr<<<(256 * 512 + 255) / 256, 256>>>(Wd3, wd3h, wd3l, 256 * 512);
    tsplit<<<(768 * 512 + 255) / 256, 256>>>(Wp1, wp1th, wp1tl, 768, 512);
    tsplit<<<(256 * 512 + 255) / 256, 256>>>(Wp1 + 768 * HID, wp1bh, wp1bl, 256, 512);

    // 1) hats = relu(NEs @ Wa + ba)  (fp32 + hi/lo outputs)
    mma_gemm<<<dim3(2, N_TOT / 128), 256>>>(NEh, NEl, wah, wal, ba,
                                            hats, hh, hl, N_TOT, DIM, DIM, 1);

    // 2) segment max + select + state_seq (fp32 + hi/lo)
    seg_reduce<<<GRP, DIM>>>(hats, nodes, act, HAts, seqf, seqh, seql);

    // 3) TCN
    tcn_mma<<<dim3(2, 12), 256>>>(seqh, seql, wc0h, wc0l, bc0, seqf,
                                  x1f, x1h, x1l, 256, 256, 1);
    mma_gemm<<<dim3(4, 12), 256>>>(x1h, x1l, wd1h, wd1l, nullptr,
                                   resf, nullptr, nullptr, 1536, 512, 256, 0);
    tcn_mma<<<dim3(4, 12), 256>>>(x1h, x1l, wc1h, wc1l, bc1, resf,
                                  x2f, x2h, x2l, 256, 512, 2);
    tcn_mma<<<dim3(4, 12), 256>>>(x2h, x2l, wc2h, wc2l, bc2, x2f,
                                  x1f, x1h, x1l, 512, 512, 4);
    mma_gemm<<<dim3(2, 12), 256>>>(x1h, x1l, wd3h, wd3l, nullptr,
                                   resf, nullptr, nullptr, 1536, 256, 512, 0);
    tcn_mma<<<dim3(2, 12), 256>>>(x1h, x1l, wc3h, wc3l, bc3, resf,
                                  x2f, x2h, x2l, 512, 256, 8);

    // 4) state_HS (hi/lo) and group term GT = sHS @ Wp1top + bp1
    build_sHS<<<GRP, DIM>>>(query, x2f, HAts, sHSh, sHSl);
    mma_gemm<<<dim3(4, 4), 256>>>(sHSh, sHSl, wp1th, wp1tl, bp1,
                                  GT, nullptr, nullptr, GRP, HID, 768, 0);

    // 5) fused final GEMM + Wp2 reduction
    final_mma<<<GRP, 256>>>(hh, hl, wp1bh, wp1bl, GT, Wp2, bp2, out);
}

// round 6
// speedup vs baseline: 2.3436x; 2.1152x over previous
#include <cuda_runtime.h>
#include <cuda_bf16.h>
#include <cstdint>

#define N_TOT 65536
#define GRP   512
#define PER   128
#define DIM   256
#define SEQL  1534
#define HID   512
#define KCH   32

typedef __nv_bfloat16 bf16;

// ---------------- scratch (device globals; no allocation allowed) ----------
__device__ bf16  g_NEh [N_TOT * DIM];
__device__ bf16  g_NEl [N_TOT * DIM];
__device__ bf16  g_hh  [N_TOT * DIM];
__device__ bf16  g_hl  [N_TOT * DIM];
__device__ float g_HAts[GRP * DIM];
__device__ float g_seqf[1536 * DIM];
__device__ bf16  g_seqh[1536 * DIM];
__device__ bf16  g_seql[1536 * DIM];
__device__ float g_x1f [1536 * 512];
__device__ bf16  g_x1h [1536 * 512];
__device__ bf16  g_x1l [1536 * 512];
__device__ float g_x2f [1536 * 512];
__device__ bf16  g_x2h [1536 * 512];
__device__ bf16  g_x2l [1536 * 512];
__device__ float g_resf[1536 * 512];
__device__ bf16  g_wah [DIM * DIM];
__device__ bf16  g_wal [DIM * DIM];
__device__ bf16  g_wc0h[3 * 256 * 256];
__device__ bf16  g_wc0l[3 * 256 * 256];
__device__ bf16  g_wc1h[3 * 512 * 256];
__device__ bf16  g_wc1l[3 * 512 * 256];
__device__ bf16  g_wc2h[3 * 512 * 512];
__device__ bf16  g_wc2l[3 * 512 * 512];
__device__ bf16  g_wc3h[3 * 256 * 512];
__device__ bf16  g_wc3l[3 * 256 * 512];
__device__ bf16  g_wd1h[512 * 256];
__device__ bf16  g_wd1l[512 * 256];
__device__ bf16  g_wd3h[256 * 512];
__device__ bf16  g_wd3l[256 * 512];
__device__ bf16  g_wp1th[512 * 768];
__device__ bf16  g_wp1tl[512 * 768];
__device__ bf16  g_wp1bh[512 * 256];
__device__ bf16  g_wp1bl[512 * 256];
__device__ bf16  g_sHSh[GRP * 768];
__device__ bf16  g_sHSl[GRP * 768];
__device__ float g_GT  [GRP * 512];

// ---------------- low-level helpers -----------------------------------------
__device__ __forceinline__ uint32_t smem_u32(const void* p) {
    uint32_t a;
    asm("{ .reg .u64 t; cvta.to.shared.u64 t, %1; cvt.u32.u64 %0, t; }"
        : "=r"(a) : "l"(p));
    return a;
}
static __device__ __forceinline__ uint32_t SWZ(uint32_t off) {
    return off ^ ((off >> 3) & 0x70);
}
__device__ __forceinline__ void mma_bf16(float* c, const uint32_t* a, const uint32_t* b) {
    asm volatile(
        "mma.sync.aligned.m16n8k16.row.col.f32.bf16.bf16.f32 "
        "{%0,%1,%2,%3}, {%4,%5,%6,%7}, {%8,%9}, {%0,%1,%2,%3};\n"
        : "+f"(c[0]), "+f"(c[1]), "+f"(c[2]), "+f"(c[3])
        : "r"(a[0]), "r"(a[1]), "r"(a[2]), "r"(a[3]), "r"(b[0]), "r"(b[1]));
}
__device__ __forceinline__ void ldm_x4(uint32_t* r, uint32_t a) {
    asm volatile("ldmatrix.sync.aligned.m8n8.x4.shared.b16 {%0,%1,%2,%3}, [%4];"
        : "=r"(r[0]), "=r"(r[1]), "=r"(r[2]), "=r"(r[3]) : "r"(a));
}
#define CP16(dst, src, pred) do {                                              \
    int _sz = (pred) ? 16 : 0;                                                 \
    asm volatile("cp.async.cg.shared.global [%0], [%1], 16, %2;"               \
        :: "r"(dst), "l"(src), "r"(_sz) : "memory"); } while (0)
#define CP_COMMIT() asm volatile("cp.async.commit_group;" ::: "memory")
#define CP_WAIT1()  asm volatile("cp.async.wait_group 1;" ::: "memory")
#define CP_WAIT0()  asm volatile("cp.async.wait_group 0;" ::: "memory")

#define STAGE_BYTES 24576u
#define DYN_SMEM    (2 * 24576 + 1024)

// ---------------- split helpers ---------------------------------------------
__device__ __forceinline__ void split2(float v, bf16& h, bf16& l) {
    h = __float2bfloat16(v);
    l = __float2bfloat16(v - __bfloat162float(h));
}
__global__ void split_arr(const float* __restrict__ x, bf16* __restrict__ h,
                          bf16* __restrict__ l, int n)
{
    int i = blockIdx.x * 256 + threadIdx.x;
    if (i < n) { bf16 a, b; split2(x[i], a, b); h[i] = a; l[i] = b; }
}
__global__ void tsplit(const float* __restrict__ w, bf16* __restrict__ h,
                       bf16* __restrict__ l, int K, int N)
{
    int i = blockIdx.x * 256 + threadIdx.x;
    if (i < K * N) {
        int k = i / N, n = i % N;
        bf16 a, b; split2(w[i], a, b);
        h[(size_t)n * K + k] = a;
        l[(size_t)n * K + k] = b;
    }
}
__global__ void split_conv(const float* __restrict__ w, bf16* __restrict__ h,
                           bf16* __restrict__ l, int Cout, int Cin)
{
    int i = blockIdx.x * 256 + threadIdx.x;
    if (i < Cout * Cin * 3) {
        int j  = i % 3;
        int ci = (i / 3) % Cin;
        int co = i / (3 * Cin);
        bf16 a, b; split2(w[i], a, b);
        size_t d = ((size_t)j * Cout + co) * Cin + ci;
        h[d] = a; l[d] = b;
    }
}

// ---------------- warp compute for one k32 chunk -----------------------------
// smem tiles: A 128 rows x 128B ([32 hi bf16 | 32 lo bf16]), B 64 rows x 128B.
// warp tile 32x32: wm in {0,32,64,96}, wn in {0,32}.
__device__ __forceinline__ void compute_chunk(uint32_t Ab, uint32_t Bb,
                                              int wm, int wn, int lane,
                                              float acc[2][4][4])
{
    int l7 = lane & 7;
    int b3 = (lane >> 3) & 1;
    int b4 = (lane >> 4) & 1;
    #pragma unroll
    for (int ks = 0; ks < 2; ks++) {
        int colb = ks * 32;
        uint32_t bh[4][2], bl[4][2];
        #pragma unroll
        for (int pp = 0; pp < 2; pp++) {
            // B: bit3 -> k+8, bit4 -> n+8
            int nrow = wn + pp * 16 + b4 * 8 + l7;
            uint32_t off = nrow * 128 + colb + b3 * 16;
            uint32_t rh[4], rl[4];
            ldm_x4(rh, Bb + SWZ(off));
            ldm_x4(rl, Bb + SWZ(off + 64));
            bh[pp * 2 + 0][0] = rh[0]; bh[pp * 2 + 0][1] = rh[1];
            bh[pp * 2 + 1][0] = rh[2]; bh[pp * 2 + 1][1] = rh[3];
            bl[pp * 2 + 0][0] = rl[0]; bl[pp * 2 + 0][1] = rl[1];
            bl[pp * 2 + 1][0] = rl[2]; bl[pp * 2 + 1][1] = rl[3];
        }
        #pragma unroll
        for (int mt = 0; mt < 2; mt++) {
            // A: bit3 -> m+8, bit4 -> k+8
            int arow = wm + mt * 16 + b3 * 8 + l7;
            uint32_t off = arow * 128 + colb + b4 * 16;
            uint32_t ah[4], al[4];
            ldm_x4(ah, Ab + SWZ(off));
            ldm_x4(al, Ab + SWZ(off + 64));
            #pragma unroll
            for (int bt = 0; bt < 4; bt++) {
                mma_bf16(acc[mt][bt], ah, bh[bt]);
                mma_bf16(acc[mt][bt], ah, bl[bt]);
                mma_bf16(acc[mt][bt], al, bh[bt]);
            }
        }
    }
}

// ---------------- generic GEMM: C = epi( sum_p A(shift_p) @ W_p^T ) ---------
// A: [M][K] hi/lo bf16. W: [npass][N][K] hi/lo. grid (N/64, M/128), 256 thr.
__global__ __launch_bounds__(256, 2)
void mma_gemm(const bf16* __restrict__ Agh, const bf16* __restrict__ Agl,
              const bf16* __restrict__ Wgh, const bf16* __restrict__ Wgl,
              const float* __restrict__ bias, const float* __restrict__ Rf,
              float* __restrict__ Cf, bf16* __restrict__ Ch, bf16* __restrict__ Cl,
              int Mv, int N, int K, int npass, int dil, int doRelu)
{
    extern __shared__ char dyn[];
    uint32_t sbase = (smem_u32(dyn) + 1023u) & ~1023u;
    int tid = threadIdx.x, lane = tid & 31, w = tid >> 5;
    int wm = (w & 3) * 32, wn = (w >> 2) * 32;
    int row0 = blockIdx.y * 128, col0 = blockIdx.x * 64;
    int kch = K / KCH;
    int nch = npass * kch;

    auto load_stage = [&](int c, int s) {
        int p  = c / kch;
        int k0 = (c - p * kch) * KCH;
        int shift = (npass == 3) ? (2 - p) * dil : 0;
        uint32_t Ab = sbase + (uint32_t)s * STAGE_BYTES;
        uint32_t Bb = Ab + 16384u;
        const bf16* Wph = Wgh + (size_t)p * N * K;
        const bf16* Wpl = Wgl + (size_t)p * N * K;
        #pragma unroll
        for (int t = 0; t < 4; t++) {
            int idx = tid + t * 256;
            int row = idx >> 3, sub = idx & 7, half = sub >> 2, q = sub & 3;
            int ta = row0 + row - shift;
            const bf16* src = (half ? Agl : Agh)
                              + (size_t)(ta < 0 ? 0 : ta) * K + k0 + q * 8;
            uint32_t dst = Ab + SWZ(row * 128 + half * 64 + q * 16);
            CP16(dst, src, ta >= 0);
        }
        #pragma unroll
        for (int t = 0; t < 2; t++) {
            int idx = tid + t * 256;
            int row = idx >> 3, sub = idx & 7, half = sub >> 2, q = sub & 3;
            const bf16* src = (half ? Wpl : Wph)
                              + (size_t)(col0 + row) * K + k0 + q * 8;
            uint32_t dst = Bb + SWZ(row * 128 + half * 64 + q * 16);
            CP16(dst, src, 1);
        }
    };

    float acc[2][4][4] = {};
    load_stage(0, 0); CP_COMMIT();
    if (nch > 1) { load_stage(1, 1); CP_COMMIT(); }
    for (int c = 0; c < nch; c++) {
        if (c + 1 < nch) { CP_WAIT1(); } else { CP_WAIT0(); }
        __syncthreads();
        uint32_t Ab = sbase + (uint32_t)(c & 1) * STAGE_BYTES;
        compute_chunk(Ab, Ab + 16384u, wm, wn, lane, acc);
        __syncthreads();
        if (c + 2 < nch) { load_stage(c + 2, c & 1); CP_COMMIT(); }
    }

    // epilogue
    #pragma unroll
    for (int mt = 0; mt < 2; mt++) {
        #pragma unroll
        for (int ih = 0; ih < 2; ih++) {
            int rr = row0 + wm + mt * 16 + ih * 8 + (lane >> 2);
            if (rr >= Mv) continue;
            #pragma unroll
            for (int bt = 0; bt < 4; bt++) {
                int cc = col0 + wn + bt * 8 + (lane & 3) * 2;
                size_t idx = (size_t)rr * N + cc;
                float v0 = acc[mt][bt][ih * 2 + 0];
                float v1 = acc[mt][bt][ih * 2 + 1];
                if (bias) { v0 += bias[cc]; v1 += bias[cc + 1]; }
                if (doRelu) { v0 = fmaxf(v0, 0.f); v1 = fmaxf(v1, 0.f); }
                if (Rf) {
                    float2 rv = *(const float2*)(Rf + idx);
                    v0 = fmaxf(v0 + rv.x, 0.f);
                    v1 = fmaxf(v1 + rv.y, 0.f);
                }
                if (Cf) *(float2*)(Cf + idx) = make_float2(v0, v1);
                if (Ch) {
                    bf16 h0, l0, h1, l1;
                    split2(v0, h0, l0); split2(v1, h1, l1);
                    __nv_bfloat162 hp = {h0, h1}, lp = {l0, l1};
                    *(__nv_bfloat162*)(Ch + idx) = hp;
                    *(__nv_bfloat162*)(Cl + idx) = lp;
                }
            }
        }
    }
}

// ---------------- fused final: out = relu(hats@Wp1bot + GT[g]) @ Wp2 + bp2 --
// one block per group; 8 n-tiles of 64, K=256 (8 k-chunks each) -> 64 chunks.
__global__ __launch_bounds__(256, 2)
void final_mma(const bf16* __restrict__ Hh, const bf16* __restrict__ Hl,
               const bf16* __restrict__ Bgh, const bf16* __restrict__ Bgl,
               const float* __restrict__ GT, const float* __restrict__ W2,
               const float* __restrict__ bp2, float* __restrict__ out)
{
    extern __shared__ char dyn[];
    __shared__ float sGT[512], sW2[512], sred[128][2];
    uint32_t sbase = (smem_u32(dyn) + 1023u) & ~1023u;
    int g = blockIdx.x;
    int tid = threadIdx.x, lane = tid & 31, w = tid >> 5;
    int wm = (w & 3) * 32, wn = (w >> 2) * 32;

    for (int i = tid; i < 512; i += 256) {
        sGT[i] = GT[(size_t)g * 512 + i];
        sW2[i] = W2[i];
    }

    const bf16* Ah = Hh + (size_t)g * PER * DIM;
    const bf16* Al = Hl + (size_t)g * PER * DIM;

    auto load_stage = [&](int c, int s) {
        int nt = c >> 3;
        int k0 = (c & 7) * KCH;
        uint32_t Ab = sbase + (uint32_t)s * STAGE_BYTES;
        uint32_t Bb = Ab + 16384u;
        #pragma unroll
        for (int t = 0; t < 4; t++) {
            int idx = tid + t * 256;
            int row = idx >> 3, sub = idx & 7, half = sub >> 2, q = sub & 3;
            const bf16* src = (half ? Al : Ah) + (size_t)row * DIM + k0 + q * 8;
            uint32_t dst = Ab + SWZ(row * 128 + half * 64 + q * 16);
            CP16(dst, src, 1);
        }
        #pragma unroll
        for (int t = 0; t < 2; t++) {
            int idx = tid + t * 256;
            int row = idx >> 3, sub = idx & 7, half = sub >> 2, q = sub & 3;
            const bf16* src = (half ? Bgl : Bgh)
                              + (size_t)(nt * 64 + row) * DIM + k0 + q * 8;
            uint32_t dst = Bb + SWZ(row * 128 + half * 64 + q * 16);
            CP16(dst, src, 1);
        }
    };

    float acc[2][4][4] = {};
    float qsum[4] = {};
    const int nch = 64;
    load_stage(0, 0); CP_COMMIT();
    load_stage(1, 1); CP_COMMIT();
    for (int c = 0; c < nch; c++) {
        if (c + 1 < nch) { CP_WAIT1(); } else { CP_WAIT0(); }
        __syncthreads();
        uint32_t Ab = sbase + (uint32_t)(c & 1) * STAGE_BYTES;
        compute_chunk(Ab, Ab + 16384u, wm, wn, lane, acc);
        __syncthreads();
        if (c + 2 < nch) { load_stage(c + 2, c & 1); CP_COMMIT(); }
        if ((c & 7) == 7) {
            int nt = c >> 3;
            #pragma unroll
            for (int mt = 0; mt < 2; mt++) {
                #pragma unroll
                for (int bt = 0; bt < 4; bt++) {
                    #pragma unroll
                    for (int i = 0; i < 4; i++) {
                        int cc = nt * 64 + wn + bt * 8 + (lane & 3) * 2 + (i & 1);
                        float hv = fmaxf(acc[mt][bt][i] + sGT[cc], 0.f);
                        qsum[mt * 2 + (i >> 1)] += hv * sW2[cc];
                        acc[mt][bt][i] = 0.f;
                    }
                }
            }
        }
    }

    #pragma unroll
    for (int mt = 0; mt < 2; mt++) {
        #pragma unroll
        for (int ih = 0; ih < 2; ih++) {
            float v = qsum[mt * 2 + ih];
            v += __shfl_xor_sync(0xffffffffu, v, 1);
            v += __shfl_xor_sync(0xffffffffu, v, 2);
            if ((lane & 3) == 0)
                sred[wm + mt * 16 + ih * 8 + (lane >> 2)][w >> 2] = v;
        }
    }
    __syncthreads();
    if (tid < 128)
        out[(size_t)g * PER + tid] = sred[tid][0] + sred[tid][1] + bp2[0];
}

// ---------------- per-group max + state_seq build ---------------------------
__global__ void seg_reduce(const bf16* __restrict__ hh, const bf16* __restrict__ hl,
                           const float* __restrict__ nodes, const int* __restrict__ act,
                           float* __restrict__ HAts, float* __restrict__ seqf,
                           bf16* __restrict__ seqh, bf16* __restrict__ seql)
{
    int g = blockIdx.x;
    int c = threadIdx.x;
    const bf16* bh = hh + (size_t)g * PER * DIM + c;
    const bf16* bl = hl + (size_t)g * PER * DIM + c;
    float m = -3.4e38f;
    #pragma unroll 4
    for (int r = 0; r < PER; r++) {
        float v = __bfloat162float(bh[(size_t)r * DIM]) + __bfloat162float(bl[(size_t)r * DIM]);
        m = fmaxf(m, v);
    }
    HAts[g * DIM + c] = m;
    auto wr = [&](int row, float v) {
        size_t id = (size_t)row * DIM + c;
        seqf[id] = v;
        bf16 a, b; split2(v, a, b);
        seqh[id] = a; seql[id] = b;
    };
    if (g < GRP - 1) {
        wr(3 * g + 0, nodes[g * DIM + c]);
        wr(3 * g + 1, m);
        int a = act[g];
        float sv = __bfloat162float(bh[(size_t)a * DIM]) + __bfloat162float(bl[(size_t)a * DIM]);
        wr(3 * g + 2, sv);
    } else {
        wr(SEQL - 1, nodes[(GRP - 1) * DIM + c]);
    }
}

// ---------------- build state_HS = [query | hs | HAts] (hi/lo) --------------
__global__ void build_sHS(const float* __restrict__ query, const float* __restrict__ xf,
                          const float* __restrict__ HAts, bf16* __restrict__ h,
                          bf16* __restrict__ l)
{
    int g = blockIdx.x, c = threadIdx.x;
    bf16 a, b;
    split2(query[g * DIM + c], a, b);
    h[g * 768 + c] = a; l[g * 768 + c] = b;
    split2(xf[(size_t)(3 * g) * DIM + c], a, b);
    h[g * 768 + 256 + c] = a; l[g * 768 + 256 + c] = b;
    split2(HAts[g * DIM + c], a, b);
    h[g * 768 + 512 + c] = a; l[g * 768 + 512 + c] = b;
}

// ---------------- launcher --------------------------------------------------
extern "C" void kernel_launch(void* const* d_in, const int* in_sizes, int n_in,
                              void* d_out, int out_size)
{
    const float* NEs   = (const float*)d_in[0];
    const float* nodes = (const float*)d_in[1];
    const float* query = (const float*)d_in[2];
    const int*   act   = (const int*)d_in[4];
    const float* Wa    = (const float*)d_in[5];
    const float* ba    = (const float*)d_in[6];
    const float* Wc0   = (const float*)d_in[7];
    const float* bc0   = (const float*)d_in[8];
    const float* Wc1   = (const float*)d_in[9];
    const float* bc1   = (const float*)d_in[10];
    const float* Wd1   = (const float*)d_in[11];
    const float* Wc2   = (const float*)d_in[12];
    const float* bc2   = (const float*)d_in[13];
    const float* Wc3   = (const float*)d_in[14];
    const float* bc3   = (const float*)d_in[15];
    const float* Wd3   = (const float*)d_in[16];
    const float* Wp1   = (const float*)d_in[17];
    const float* bp1   = (const float*)d_in[18];
    const float* Wp2   = (const float*)d_in[19];
    const float* bp2   = (const float*)d_in[20];
    float* out = (float*)d_out;

    cudaFuncSetAttribute(mma_gemm, cudaFuncAttributeMaxDynamicSharedMemorySize, DYN_SMEM);
    cudaFuncSetAttribute(final_mma, cudaFuncAttributeMaxDynamicSharedMemorySize, DYN_SMEM);

    bf16 *NEh, *NEl, *hh, *hl, *seqh, *seql, *x1h, *x1l, *x2h, *x2l;
    bf16 *wah, *wal, *wc0h, *wc0l, *wc1h, *wc1l, *wc2h, *wc2l, *wc3h, *wc3l;
    bf16 *wd1h, *wd1l, *wd3h, *wd3l, *wp1th, *wp1tl, *wp1bh, *wp1bl, *sHSh, *sHSl;
    float *HAts, *seqf, *x1f, *x2f, *resf, *GT;
    cudaGetSymbolAddress((void**)&NEh,  g_NEh);   cudaGetSymbolAddress((void**)&NEl,  g_NEl);
    cudaGetSymbolAddress((void**)&hh,   g_hh);    cudaGetSymbolAddress((void**)&hl,   g_hl);
    cudaGetSymbolAddress((void**)&HAts, g_HAts);
    cudaGetSymbolAddress((void**)&seqf, g_seqf);
    cudaGetSymbolAddress((void**)&seqh, g_seqh);  cudaGetSymbolAddress((void**)&seql, g_seql);
    cudaGetSymbolAddress((void**)&x1f,  g_x1f);
    cudaGetSymbolAddress((void**)&x1h,  g_x1h);   cudaGetSymbolAddress((void**)&x1l,  g_x1l);
    cudaGetSymbolAddress((void**)&x2f,  g_x2f);
    cudaGetSymbolAddress((void**)&x2h,  g_x2h);   cudaGetSymbolAddress((void**)&x2l,  g_x2l);
    cudaGetSymbolAddress((void**)&resf, g_resf);
    cudaGetSymbolAddress((void**)&wah,  g_wah);   cudaGetSymbolAddress((void**)&wal,  g_wal);
    cudaGetSymbolAddress((void**)&wc0h, g_wc0h);  cudaGetSymbolAddress((void**)&wc0l, g_wc0l);
    cudaGetSymbolAddress((void**)&wc1h, g_wc1h);  cudaGetSymbolAddress((void**)&wc1l, g_wc1l);
    cudaGetSymbolAddress((void**)&wc2h, g_wc2h);  cudaGetSymbolAddress((void**)&wc2l, g_wc2l);
    cudaGetSymbolAddress((void**)&wc3h, g_wc3h);  cudaGetSymbolAddress((void**)&wc3l, g_wc3l);
    cudaGetSymbolAddress((void**)&wd1h, g_wd1h);  cudaGetSymbolAddress((void**)&wd1l, g_wd1l);
    cudaGetSymbolAddress((void**)&wd3h, g_wd3h);  cudaGetSymbolAddress((void**)&wd3l, g_wd3l);
    cudaGetSymbolAddress((void**)&wp1th, g_wp1th); cudaGetSymbolAddress((void**)&wp1tl, g_wp1tl);
    cudaGetSymbolAddress((void**)&wp1bh, g_wp1bh); cudaGetSymbolAddress((void**)&wp1bl, g_wp1bl);
    cudaGetSymbolAddress((void**)&sHSh, g_sHSh);  cudaGetSymbolAddress((void**)&sHSl, g_sHSl);
    cudaGetSymbolAddress((void**)&GT,   g_GT);

    // launches 0..4 = prep, so ncu (-s 5 -c 1) profiles the hats GEMM
    split_arr<<<(N_TOT * DIM + 255) / 256, 256>>>(NEs, NEh, NEl, N_TOT * DIM);         // 0
    tsplit<<<(256 * 256 + 255) / 256, 256>>>(Wa, wah, wal, 256, 256);                  // 1
    split_conv<<<(256 * 256 * 3 + 255) / 256, 256>>>(Wc0, wc0h, wc0l, 256, 256);       // 2
    split_conv<<<(512 * 256 * 3 + 255) / 256, 256>>>(Wc1, wc1h, wc1l, 512, 256);       // 3
    split_conv<<<(512 * 512 * 3 + 255) / 256, 256>>>(Wc2, wc2h, wc2l, 512, 512);       // 4

    // 1) hats = relu(NEs @ Wa + ba) -> hi/lo                                           // 5 (profiled)
    mma_gemm<<<dim3(DIM / 64, N_TOT / 128), 256, DYN_SMEM>>>(NEh, NEl, wah, wal, ba,
        nullptr, nullptr, hh, hl, N_TOT, DIM, DIM, 1, 0, 1);

    // remaining weight prep
    split_conv<<<(256 * 512 * 3 + 255) / 256, 256>>>(Wc3, wc3h, wc3l, 256, 512);
    split_arr<<<(512 * 256 + 255) / 256, 256>>>(Wd1, wd1h, wd1l, 512 * 256);
    split_arr<<<(256 * 512 + 255) / 256, 256>>>(Wd3, wd3h, wd3l, 256 * 512);
    tsplit<<<(768 * 512 + 255) / 256, 256>>>(Wp1, wp1th, wp1tl, 768, 512);
    tsplit<<<(256 * 512 + 255) / 256, 256>>>(Wp1 + 768 * HID, wp1bh, wp1bl, 256, 512);

    // 2) segment max + select + state_seq
    seg_reduce<<<GRP, DIM>>>(hh, hl, nodes, act, HAts, seqf, seqh, seql);

    // 3) TCN  (M padded to 1536; Mv = SEQL masks the tail)
    mma_gemm<<<dim3(4, 12), 256, DYN_SMEM>>>(seqh, seql, wc0h, wc0l, bc0, seqf,
        x1f, x1h, x1l, SEQL, 256, 256, 3, 1, 1);
    mma_gemm<<<dim3(8, 12), 256, DYN_SMEM>>>(x1h, x1l, wd1h, wd1l, nullptr, nullptr,
        resf, nullptr, nullptr, SEQL, 512, 256, 1, 0, 0);
    mma_gemm<<<dim3(8, 12), 256, DYN_SMEM>>>(x1h, x1l, wc1h, wc1l, bc1, resf,
        x2f, x2h, x2l, SEQL, 512, 256, 3, 2, 1);
    mma_gemm<<<dim3(8, 12), 256, DYN_SMEM>>>(x2h, x2l, wc2h, wc2l, bc2, x2f,
        x1f, x1h, x1l, SEQL, 512, 512, 3, 4, 1);
    mma_gemm<<<dim3(4, 12), 256, DYN_SMEM>>>(x1h, x1l, wd3h, wd3l, nullptr, nullptr,
        resf, nullptr, nullptr, SEQL, 256, 512, 1, 0, 0);
    mma_gemm<<<dim3(4, 12), 256, DYN_SMEM>>>(x1h, x1l, wc3h, wc3l, bc3, resf,
        x2f, x2h, x2l, SEQL, 256, 512, 3, 8, 1);

    // 4) state_HS and group term GT = sHS @ Wp1top + bp1
    build_sHS<<<GRP, DIM>>>(query, x2f, HAts, sHSh, sHSl);
    mma_gemm<<<dim3(8, 4), 256, DYN_SMEM>>>(sHSh, sHSl, wp1th, wp1tl, bp1, nullptr,
        GT, nullptr, nullptr, GRP, HID, 768, 1, 0, 0);

    // 5) fused final GEMM + Wp2 reduction
    final_mma<<<GRP, 256, DYN_SMEM>>>(hh, hl, wp1bh, wp1bl, GT, Wp2, bp2, out);
}

// round 7
// speedup vs baseline: 2.7008x; 1.1524x over previous
#include <cuda_runtime.h>
#include <cuda_bf16.h>
#include <cstdint>

#define N_TOT 65536
#define GRP   512
#define PER   128
#define DIM   256
#define SEQL  1534
#define HID   512
#define KCH   32

typedef __nv_bfloat16 bf16;

// ---------------- scratch (device globals; no allocation allowed) ----------
__device__ bf16  g_NEh [N_TOT * DIM];
__device__ bf16  g_NEl [N_TOT * DIM];
__device__ bf16  g_hh  [N_TOT * DIM];
__device__ bf16  g_hl  [N_TOT * DIM];
__device__ float g_HAts[GRP * DIM];
__device__ float g_seqf[1536 * DIM];
__device__ bf16  g_seqh[1536 * DIM];
__device__ bf16  g_seql[1536 * DIM];
__device__ bf16  g_x1h [1536 * 512];
__device__ bf16  g_x1l [1536 * 512];
__device__ float g_x2f [1536 * 512];
__device__ bf16  g_x2h [1536 * 512];
__device__ bf16  g_x2l [1536 * 512];
__device__ bf16  g_wah [DIM * DIM];
__device__ bf16  g_wal [DIM * DIM];
__device__ bf16  g_wc0h[3 * 256 * 256];
__device__ bf16  g_wc0l[3 * 256 * 256];
__device__ bf16  g_wc1h[3 * 512 * 256];
__device__ bf16  g_wc1l[3 * 512 * 256];
__device__ bf16  g_wc2h[3 * 512 * 512];
__device__ bf16  g_wc2l[3 * 512 * 512];
__device__ bf16  g_wc3h[3 * 256 * 512];
__device__ bf16  g_wc3l[3 * 256 * 512];
__device__ bf16  g_wd1h[512 * 256];
__device__ bf16  g_wd1l[512 * 256];
__device__ bf16  g_wd3h[256 * 512];
__device__ bf16  g_wd3l[256 * 512];
__device__ bf16  g_wp1th[512 * 768];
__device__ bf16  g_wp1tl[512 * 768];
__device__ bf16  g_wp1bh[512 * 256];
__device__ bf16  g_wp1bl[512 * 256];
__device__ bf16  g_sHSh[GRP * 768];
__device__ bf16  g_sHSl[GRP * 768];
__device__ float g_GT  [GRP * 512];

// ---------------- low-level helpers -----------------------------------------
__device__ __forceinline__ uint32_t smem_u32(const void* p) {
    uint32_t a;
    asm("{ .reg .u64 t; cvta.to.shared.u64 t, %1; cvt.u32.u64 %0, t; }"
        : "=r"(a) : "l"(p));
    return a;
}
static __device__ __forceinline__ uint32_t SWZ(uint32_t off) {
    return off ^ ((off >> 3) & 0x70);
}
__device__ __forceinline__ void mma_bf16(float* c, const uint32_t* a, const uint32_t* b) {
    asm volatile(
        "mma.sync.aligned.m16n8k16.row.col.f32.bf16.bf16.f32 "
        "{%0,%1,%2,%3}, {%4,%5,%6,%7}, {%8,%9}, {%0,%1,%2,%3};\n"
        : "+f"(c[0]), "+f"(c[1]), "+f"(c[2]), "+f"(c[3])
        : "r"(a[0]), "r"(a[1]), "r"(a[2]), "r"(a[3]), "r"(b[0]), "r"(b[1]));
}
__device__ __forceinline__ void ldm_x4(uint32_t* r, uint32_t a) {
    asm volatile("ldmatrix.sync.aligned.m8n8.x4.shared.b16 {%0,%1,%2,%3}, [%4];"
        : "=r"(r[0]), "=r"(r[1]), "=r"(r[2]), "=r"(r[3]) : "r"(a));
}
#define CP16(dst, src, pred) do {                                              \
    int _sz = (pred) ? 16 : 0;                                                 \
    asm volatile("cp.async.cg.shared.global [%0], [%1], 16, %2;"               \
        :: "r"(dst), "l"(src), "r"(_sz) : "memory"); } while (0)
#define CP_COMMIT() asm volatile("cp.async.commit_group;" ::: "memory")
#define CP_WAIT1()  asm volatile("cp.async.wait_group 1;" ::: "memory")
#define CP_WAIT0()  asm volatile("cp.async.wait_group 0;" ::: "memory")

// ---------------- split helpers ---------------------------------------------
__device__ __forceinline__ void split2(float v, bf16& h, bf16& l) {
    h = __float2bfloat16(v);
    l = __float2bfloat16(v - __bfloat162float(h));
}
__global__ void split_arr(const float* __restrict__ x, bf16* __restrict__ h,
                          bf16* __restrict__ l, int n)
{
    int i = blockIdx.x * 256 + threadIdx.x;
    if (i < n) { bf16 a, b; split2(x[i], a, b); h[i] = a; l[i] = b; }
}

__device__ __forceinline__ void d_tsplit(const float* w, bf16* h, bf16* l,
                                         int K, int N, int i)
{
    if (i < K * N) {
        int k = i / N, n = i % N;
        bf16 a, b; split2(w[i], a, b);
        h[(size_t)n * K + k] = a;
        l[(size_t)n * K + k] = b;
    }
}
__device__ __forceinline__ void d_conv(const float* w, bf16* h, bf16* l,
                                       int Cout, int Cin, int i)
{
    if (i < Cout * Cin * 3) {
        int j  = i % 3;
        int ci = (i / 3) % Cin;
        int co = i / (3 * Cin);
        bf16 a, b; split2(w[i], a, b);
        size_t d = ((size_t)j * Cout + co) * Cin + ci;
        h[d] = a; l[d] = b;
    }
}
__device__ __forceinline__ void d_arr(const float* w, bf16* h, bf16* l, int n, int i)
{
    if (i < n) { bf16 a, b; split2(w[i], a, b); h[i] = a; l[i] = b; }
}

// one kernel for ALL weight splits (block-range dispatch)
__global__ void split_weights(
    const float* Wa, const float* Wc0, const float* Wc1, const float* Wc2,
    const float* Wc3, const float* Wd1, const float* Wd3, const float* Wp1,
    bf16* wah, bf16* wal, bf16* wc0h, bf16* wc0l, bf16* wc1h, bf16* wc1l,
    bf16* wc2h, bf16* wc2l, bf16* wc3h, bf16* wc3l, bf16* wd1h, bf16* wd1l,
    bf16* wd3h, bf16* wd3l, bf16* wp1th, bf16* wp1tl, bf16* wp1bh, bf16* wp1bl)
{
    int b = blockIdx.x, t = threadIdx.x;
    if (b < 256)        { d_tsplit(Wa, wah, wal, 256, 256, b * 256 + t); return; }
    b -= 256;
    if (b < 768)        { d_conv(Wc0, wc0h, wc0l, 256, 256, b * 256 + t); return; }
    b -= 768;
    if (b < 1536)       { d_conv(Wc1, wc1h, wc1l, 512, 256, b * 256 + t); return; }
    b -= 1536;
    if (b < 3072)       { d_conv(Wc2, wc2h, wc2l, 512, 512, b * 256 + t); return; }
    b -= 3072;
    if (b < 1536)       { d_conv(Wc3, wc3h, wc3l, 256, 512, b * 256 + t); return; }
    b -= 1536;
    if (b < 512)        { d_arr(Wd1, wd1h, wd1l, 512 * 256, b * 256 + t); return; }
    b -= 512;
    if (b < 512)        { d_arr(Wd3, wd3h, wd3l, 256 * 512, b * 256 + t); return; }
    b -= 512;
    if (b < 1536)       { d_tsplit(Wp1, wp1th, wp1tl, 768, 512, b * 256 + t); return; }
    b -= 1536;
    if (b < 512)        { d_tsplit(Wp1 + 768 * 512, wp1bh, wp1bl, 256, 512, b * 256 + t); }
}
#define SPLITW_BLOCKS (256 + 768 + 1536 + 3072 + 1536 + 512 + 512 + 1536 + 512)

// ---------------- warp compute for one k32 chunk -----------------------------
// smem A: MR rows x 128B ([32 hi bf16 | 32 lo bf16]); smem B: NR rows x 128B.
// warp tile = 32 (m) x NBT*8 (n).
template<int NBT>
__device__ __forceinline__ void compute_chunk_t(uint32_t Ab, uint32_t Bb,
                                                int wm, int wn, int lane,
                                                float acc[2][NBT][4])
{
    int l7 = lane & 7;
    int b3 = (lane >> 3) & 1;
    int b4 = (lane >> 4) & 1;
    #pragma unroll
    for (int ks = 0; ks < 2; ks++) {
        int colb = ks * 32;
        uint32_t bh[NBT][2], bl[NBT][2];
        #pragma unroll
        for (int pp = 0; pp < NBT / 2; pp++) {
            int nrow = wn + pp * 16 + b4 * 8 + l7;
            uint32_t off = nrow * 128 + colb + b3 * 16;
            uint32_t rh[4], rl[4];
            ldm_x4(rh, Bb + SWZ(off));
            ldm_x4(rl, Bb + SWZ(off + 64));
            bh[pp * 2 + 0][0] = rh[0]; bh[pp * 2 + 0][1] = rh[1];
            bh[pp * 2 + 1][0] = rh[2]; bh[pp * 2 + 1][1] = rh[3];
            bl[pp * 2 + 0][0] = rl[0]; bl[pp * 2 + 0][1] = rl[1];
            bl[pp * 2 + 1][0] = rl[2]; bl[pp * 2 + 1][1] = rl[3];
        }
        #pragma unroll
        for (int mt = 0; mt < 2; mt++) {
            int arow = wm + mt * 16 + b3 * 8 + l7;
            uint32_t off = arow * 128 + colb + b4 * 16;
            uint32_t ah[4], al[4];
            ldm_x4(ah, Ab + SWZ(off));
            ldm_x4(al, Ab + SWZ(off + 64));
            #pragma unroll
            for (int bt = 0; bt < NBT; bt++) {
                mma_bf16(acc[mt][bt], ah, bh[bt]);
                mma_bf16(acc[mt][bt], ah, bl[bt]);
                mma_bf16(acc[mt][bt], al, bh[bt]);
            }
        }
    }
}

// ---------------- hats GEMM: 128x128 tiles, 256 threads ----------------------
// C = relu(A@W^T + bias) -> hi/lo split only. grid (N/128, M/128).
#define G128_STAGE 32768u
#define G128_DYN   (2 * 32768 + 1024)
__global__ __launch_bounds__(256, 2)
void gemm128(const bf16* __restrict__ Agh, const bf16* __restrict__ Agl,
             const bf16* __restrict__ Wgh, const bf16* __restrict__ Wgl,
             const float* __restrict__ bias,
             bf16* __restrict__ Ch, bf16* __restrict__ Cl, int N, int K)
{
    extern __shared__ char dyn[];
    uint32_t sbase = (smem_u32(dyn) + 1023u) & ~1023u;
    int tid = threadIdx.x, lane = tid & 31, w = tid >> 5;
    int wm = (w & 3) * 32, wn = (w >> 2) * 64;
    int row0 = blockIdx.y * 128, col0 = blockIdx.x * 128;
    int nch = K / KCH;

    auto load_stage = [&](int c, int s) {
        int k0 = c * KCH;
        uint32_t Ab = sbase + (uint32_t)s * G128_STAGE;
        uint32_t Bb = Ab + 16384u;
        #pragma unroll
        for (int t = 0; t < 4; t++) {
            int idx = tid + t * 256;
            int row = idx >> 3, sub = idx & 7, half = sub >> 2, q = sub & 3;
            const bf16* src = (half ? Agl : Agh) + (size_t)(row0 + row) * K + k0 + q * 8;
            CP16(Ab + SWZ(row * 128 + half * 64 + q * 16), src, 1);
        }
        #pragma unroll
        for (int t = 0; t < 4; t++) {
            int idx = tid + t * 256;
            int row = idx >> 3, sub = idx & 7, half = sub >> 2, q = sub & 3;
            const bf16* src = (half ? Wgl : Wgh) + (size_t)(col0 + row) * K + k0 + q * 8;
            CP16(Bb + SWZ(row * 128 + half * 64 + q * 16), src, 1);
        }
    };

    float acc[2][8][4] = {};
    load_stage(0, 0); CP_COMMIT();
    load_stage(1, 1); CP_COMMIT();
    for (int c = 0; c < nch; c++) {
        if (c + 1 < nch) { CP_WAIT1(); } else { CP_WAIT0(); }
        __syncthreads();
        uint32_t Ab = sbase + (uint32_t)(c & 1) * G128_STAGE;
        compute_chunk_t<8>(Ab, Ab + 16384u, wm, wn, lane, acc);
        __syncthreads();
        if (c + 2 < nch) { load_stage(c + 2, c & 1); CP_COMMIT(); }
    }

    #pragma unroll
    for (int mt = 0; mt < 2; mt++) {
        #pragma unroll
        for (int ih = 0; ih < 2; ih++) {
            int rr = row0 + wm + mt * 16 + ih * 8 + (lane >> 2);
            #pragma unroll
            for (int bt = 0; bt < 8; bt++) {
                int cc = col0 + wn + bt * 8 + (lane & 3) * 2;
                float v0 = fmaxf(acc[mt][bt][ih * 2 + 0] + bias[cc], 0.f);
                float v1 = fmaxf(acc[mt][bt][ih * 2 + 1] + bias[cc + 1], 0.f);
                size_t idx = (size_t)rr * N + cc;
                bf16 h0, l0, h1, l1;
                split2(v0, h0, l0); split2(v1, h1, l1);
                __nv_bfloat162 hp = {h0, h1}, lp = {l0, l1};
                *(__nv_bfloat162*)(Ch + idx) = hp;
                *(__nv_bfloat162*)(Cl + idx) = lp;
            }
        }
    }
}

// ---------------- TCN / GT GEMM: 64x64 tiles, 128 threads --------------------
// passes 0..2: conv taps (shift (2-p)*dil); pass 3 (DUAL): Wd residual.
// epi: v = acc+bias; if relu v=relu(v); res=DUAL?accR:Rf; if res v=relu(v+res)
#define T64_STAGE 16384u
#define T64_DYN   (2 * 16384 + 1024)
template<int DUAL>
__global__ __launch_bounds__(128, 4)
void tcn64(const bf16* __restrict__ Agh, const bf16* __restrict__ Agl,
           const bf16* __restrict__ Wgh, const bf16* __restrict__ Wgl,
           const bf16* __restrict__ Wdh, const bf16* __restrict__ Wdl,
           const float* __restrict__ bias, const float* __restrict__ Rf,
           float* __restrict__ Cf, bf16* __restrict__ Ch, bf16* __restrict__ Cl,
           int Mv, int N, int K, int npass, int dil, int doRelu)
{
    extern __shared__ char dyn[];
    uint32_t sbase = (smem_u32(dyn) + 1023u) & ~1023u;
    int tid = threadIdx.x, lane = tid & 31, w = tid >> 5;
    int wm = (w & 1) * 32, wn = (w >> 1) * 32;
    int row0 = blockIdx.y * 64, col0 = blockIdx.x * 64;
    int kch = K / KCH;
    int nch = npass * kch;

    auto load_stage = [&](int c, int s) {
        int p  = c / kch;
        int k0 = (c - p * kch) * KCH;
        int shift = (p < 3 && npass >= 3) ? (2 - p) * dil : 0;
        const bf16* Ph = (p < 3) ? Wgh + (size_t)p * N * K : Wdh;
        const bf16* Pl = (p < 3) ? Wgl + (size_t)p * N * K : Wdl;
        uint32_t Ab = sbase + (uint32_t)s * T64_STAGE;
        uint32_t Bb = Ab + 8192u;
        #pragma unroll
        for (int t = 0; t < 4; t++) {
            int idx = tid + t * 128;
            int row = idx >> 3, sub = idx & 7, half = sub >> 2, q = sub & 3;
            int ta = row0 + row - shift;
            const bf16* src = (half ? Agl : Agh)
                              + (size_t)(ta < 0 ? 0 : ta) * K + k0 + q * 8;
            CP16(Ab + SWZ(row * 128 + half * 64 + q * 16), src, ta >= 0);
        }
        #pragma unroll
        for (int t = 0; t < 4; t++) {
            int idx = tid + t * 128;
            int row = idx >> 3, sub = idx & 7, half = sub >> 2, q = sub & 3;
            const bf16* src = (half ? Pl : Ph) + (size_t)(col0 + row) * K + k0 + q * 8;
            CP16(Bb + SWZ(row * 128 + half * 64 + q * 16), src, 1);
        }
    };

    float acc[2][4][4] = {};
    float accR[DUAL ? 2 : 1][DUAL ? 4 : 1][DUAL ? 4 : 1] = {};
    load_stage(0, 0); CP_COMMIT();
    if (nch > 1) { load_stage(1, 1); CP_COMMIT(); }
    for (int c = 0; c < nch; c++) {
        if (c + 1 < nch) { CP_WAIT1(); } else { CP_WAIT0(); }
        __syncthreads();
        uint32_t Ab = sbase + (uint32_t)(c & 1) * T64_STAGE;
        if (DUAL && c >= 3 * kch)
            compute_chunk_t<4>(Ab, Ab + 8192u, wm, wn, lane,
                               (float (*)[4][4])accR);
        else
            compute_chunk_t<4>(Ab, Ab + 8192u, wm, wn, lane, acc);
        __syncthreads();
        if (c + 2 < nch) { load_stage(c + 2, c & 1); CP_COMMIT(); }
    }

    #pragma unroll
    for (int mt = 0; mt < 2; mt++) {
        #pragma unroll
        for (int ih = 0; ih < 2; ih++) {
            int rr = row0 + wm + mt * 16 + ih * 8 + (lane >> 2);
            if (rr >= Mv) continue;
            #pragma unroll
            for (int bt = 0; bt < 4; bt++) {
                int cc = col0 + wn + bt * 8 + (lane & 3) * 2;
                size_t idx = (size_t)rr * N + cc;
                float v0 = acc[mt][bt][ih * 2 + 0] + bias[cc];
                float v1 = acc[mt][bt][ih * 2 + 1] + bias[cc + 1];
                if (doRelu) { v0 = fmaxf(v0, 0.f); v1 = fmaxf(v1, 0.f); }
                if (DUAL) {
                    v0 = fmaxf(v0 + accR[mt][bt][ih * 2 + 0], 0.f);
                    v1 = fmaxf(v1 + accR[mt][bt][ih * 2 + 1], 0.f);
                } else if (Rf) {
                    float2 rv = *(const float2*)(Rf + idx);
                    v0 = fmaxf(v0 + rv.x, 0.f);
                    v1 = fmaxf(v1 + rv.y, 0.f);
                }
                if (Cf) *(float2*)(Cf + idx) = make_float2(v0, v1);
                if (Ch) {
                    bf16 h0, l0, h1, l1;
                    split2(v0, h0, l0); split2(v1, h1, l1);
                    __nv_bfloat162 hp = {h0, h1}, lp = {l0, l1};
                    *(__nv_bfloat162*)(Ch + idx) = hp;
                    *(__nv_bfloat162*)(Cl + idx) = lp;
                }
            }
        }
    }
}

// ---------------- fused final: out = relu(hats@Wp1bot + GT[g]) @ Wp2 + bp2 --
#define FIN_STAGE 24576u
#define FIN_DYN   (2 * 24576 + 1024)
__global__ __launch_bounds__(256, 2)
void final_mma(const bf16* __restrict__ Hh, const bf16* __restrict__ Hl,
               const bf16* __restrict__ Bgh, const bf16* __restrict__ Bgl,
               const float* __restrict__ GT, const float* __restrict__ W2,
               const float* __restrict__ bp2, float* __restrict__ out)
{
    extern __shared__ char dyn[];
    __shared__ float sGT[512], sW2[512], sred[128][2];
    uint32_t sbase = (smem_u32(dyn) + 1023u) & ~1023u;
    int g = blockIdx.x;
    int tid = threadIdx.x, lane = tid & 31, w = tid >> 5;
    int wm = (w & 3) * 32, wn = (w >> 2) * 32;

    for (int i = tid; i < 512; i += 256) {
        sGT[i] = GT[(size_t)g * 512 + i];
        sW2[i] = W2[i];
    }

    const bf16* Ah = Hh + (size_t)g * PER * DIM;
    const bf16* Al = Hl + (size_t)g * PER * DIM;

    auto load_stage = [&](int c, int s) {
        int nt = c >> 3;
        int k0 = (c & 7) * KCH;
        uint32_t Ab = sbase + (uint32_t)s * FIN_STAGE;
        uint32_t Bb = Ab + 16384u;
        #pragma unroll
        for (int t = 0; t < 4; t++) {
            int idx = tid + t * 256;
            int row = idx >> 3, sub = idx & 7, half = sub >> 2, q = sub & 3;
            const bf16* src = (half ? Al : Ah) + (size_t)row * DIM + k0 + q * 8;
            CP16(Ab + SWZ(row * 128 + half * 64 + q * 16), src, 1);
        }
        #pragma unroll
        for (int t = 0; t < 2; t++) {
            int idx = tid + t * 256;
            int row = idx >> 3, sub = idx & 7, half = sub >> 2, q = sub & 3;
            const bf16* src = (half ? Bgl : Bgh)
                              + (size_t)(nt * 64 + row) * DIM + k0 + q * 8;
            CP16(Bb + SWZ(row * 128 + half * 64 + q * 16), src, 1);
        }
    };

    float acc[2][4][4] = {};
    float qsum[4] = {};
    const int nch = 64;
    load_stage(0, 0); CP_COMMIT();
    load_stage(1, 1); CP_COMMIT();
    for (int c = 0; c < nch; c++) {
        if (c + 1 < nch) { CP_WAIT1(); } else { CP_WAIT0(); }
        __syncthreads();
        uint32_t Ab = sbase + (uint32_t)(c & 1) * FIN_STAGE;
        compute_chunk_t<4>(Ab, Ab + 16384u, wm, wn, lane, acc);
        __syncthreads();
        if (c + 2 < nch) { load_stage(c + 2, c & 1); CP_COMMIT(); }
        if ((c & 7) == 7) {
            int nt = c >> 3;
            #pragma unroll
            for (int mt = 0; mt < 2; mt++) {
                #pragma unroll
                for (int bt = 0; bt < 4; bt++) {
                    #pragma unroll
                    for (int i = 0; i < 4; i++) {
                        int cc = nt * 64 + wn + bt * 8 + (lane & 3) * 2 + (i & 1);
                        float hv = fmaxf(acc[mt][bt][i] + sGT[cc], 0.f);
                        qsum[mt * 2 + (i >> 1)] += hv * sW2[cc];
                        acc[mt][bt][i] = 0.f;
                    }
                }
            }
        }
    }

    #pragma unroll
    for (int mt = 0; mt < 2; mt++) {
        #pragma unroll
        for (int ih = 0; ih < 2; ih++) {
            float v = qsum[mt * 2 + ih];
            v += __shfl_xor_sync(0xffffffffu, v, 1);
            v += __shfl_xor_sync(0xffffffffu, v, 2);
            if ((lane & 3) == 0)
                sred[wm + mt * 16 + ih * 8 + (lane >> 2)][w >> 2] = v;
        }
    }
    __syncthreads();
    if (tid < 128)
        out[(size_t)g * PER + tid] = sred[tid][0] + sred[tid][1] + bp2[0];
}

// ---------------- per-group max + state_seq build ---------------------------
__global__ void seg_reduce(const bf16* __restrict__ hh, const bf16* __restrict__ hl,
                           const float* __restrict__ nodes, const int* __restrict__ act,
                           float* __restrict__ HAts, float* __restrict__ seqf,
                           bf16* __restrict__ seqh, bf16* __restrict__ seql)
{
    int g = blockIdx.x;
    int c = threadIdx.x;
    const bf16* bh = hh + (size_t)g * PER * DIM + c;
    const bf16* bl = hl + (size_t)g * PER * DIM + c;
    float m = -3.4e38f;
    #pragma unroll 4
    for (int r = 0; r < PER; r++) {
        float v = __bfloat162float(bh[(size_t)r * DIM]) + __bfloat162float(bl[(size_t)r * DIM]);
        m = fmaxf(m, v);
    }
    HAts[g * DIM + c] = m;
    auto wr = [&](int row, float v) {
        size_t id = (size_t)row * DIM + c;
        seqf[id] = v;
        bf16 a, b; split2(v, a, b);
        seqh[id] = a; seql[id] = b;
    };
    if (g < GRP - 1) {
        wr(3 * g + 0, nodes[g * DIM + c]);
        wr(3 * g + 1, m);
        int a = act[g];
        float sv = __bfloat162float(bh[(size_t)a * DIM]) + __bfloat162float(bl[(size_t)a * DIM]);
        wr(3 * g + 2, sv);
    } else {
        wr(SEQL - 1, nodes[(GRP - 1) * DIM + c]);
    }
}

// ---------------- build state_HS = [query | hs | HAts] (hi/lo) --------------
__global__ void build_sHS(const float* __restrict__ query, const float* __restrict__ xf,
                          const float* __restrict__ HAts, bf16* __restrict__ h,
                          bf16* __restrict__ l)
{
    int g = blockIdx.x, c = threadIdx.x;
    bf16 a, b;
    split2(query[g * DIM + c], a, b);
    h[g * 768 + c] = a; l[g * 768 + c] = b;
    split2(xf[(size_t)(3 * g) * DIM + c], a, b);
    h[g * 768 + 256 + c] = a; l[g * 768 + 256 + c] = b;
    split2(HAts[g * DIM + c], a, b);
    h[g * 768 + 512 + c] = a; l[g * 768 + 512 + c] = b;
}

// ---------------- launcher --------------------------------------------------
extern "C" void kernel_launch(void* const* d_in, const int* in_sizes, int n_in,
                              void* d_out, int out_size)
{
    const float* NEs   = (const float*)d_in[0];
    const float* nodes = (const float*)d_in[1];
    const float* query = (const float*)d_in[2];
    const int*   act   = (const int*)d_in[4];
    const float* Wa    = (const float*)d_in[5];
    const float* ba    = (const float*)d_in[6];
    const float* Wc0   = (const float*)d_in[7];
    const float* bc0   = (const float*)d_in[8];
    const float* Wc1   = (const float*)d_in[9];
    const float* bc1   = (const float*)d_in[10];
    const float* Wd1   = (const float*)d_in[11];
    const float* Wc2   = (const float*)d_in[12];
    const float* bc2   = (const float*)d_in[13];
    const float* Wc3   = (const float*)d_in[14];
    const float* bc3   = (const float*)d_in[15];
    const float* Wd3   = (const float*)d_in[16];
    const float* Wp1   = (const float*)d_in[17];
    const float* bp1   = (const float*)d_in[18];
    const float* Wp2   = (const float*)d_in[19];
    const float* bp2   = (const float*)d_in[20];
    float* out = (float*)d_out;

    cudaFuncSetAttribute(gemm128,  cudaFuncAttributeMaxDynamicSharedMemorySize, G128_DYN);
    cudaFuncSetAttribute(tcn64<0>, cudaFuncAttributeMaxDynamicSharedMemorySize, T64_DYN);
    cudaFuncSetAttribute(tcn64<1>, cudaFuncAttributeMaxDynamicSharedMemorySize, T64_DYN);
    cudaFuncSetAttribute(final_mma, cudaFuncAttributeMaxDynamicSharedMemorySize, FIN_DYN);

    bf16 *NEh, *NEl, *hh, *hl, *seqh, *seql, *x1h, *x1l, *x2h, *x2l;
    bf16 *wah, *wal, *wc0h, *wc0l, *wc1h, *wc1l, *wc2h, *wc2l, *wc3h, *wc3l;
    bf16 *wd1h, *wd1l, *wd3h, *wd3l, *wp1th, *wp1tl, *wp1bh, *wp1bl, *sHSh, *sHSl;
    float *HAts, *seqf, *x2f, *GT;
    cudaGetSymbolAddress((void**)&NEh,  g_NEh);   cudaGetSymbolAddress((void**)&NEl,  g_NEl);
    cudaGetSymbolAddress((void**)&hh,   g_hh);    cudaGetSymbolAddress((void**)&hl,   g_hl);
    cudaGetSymbolAddress((void**)&HAts, g_HAts);
    cudaGetSymbolAddress((void**)&seqf, g_seqf);
    cudaGetSymbolAddress((void**)&seqh, g_seqh);  cudaGetSymbolAddress((void**)&seql, g_seql);
    cudaGetSymbolAddress((void**)&x1h,  g_x1h);   cudaGetSymbolAddress((void**)&x1l,  g_x1l);
    cudaGetSymbolAddress((void**)&x2f,  g_x2f);
    cudaGetSymbolAddress((void**)&x2h,  g_x2h);   cudaGetSymbolAddress((void**)&x2l,  g_x2l);
    cudaGetSymbolAddress((void**)&wah,  g_wah);   cudaGetSymbolAddress((void**)&wal,  g_wal);
    cudaGetSymbolAddress((void**)&wc0h, g_wc0h);  cudaGetSymbolAddress((void**)&wc0l, g_wc0l);
    cudaGetSymbolAddress((void**)&wc1h, g_wc1h);  cudaGetSymbolAddress((void**)&wc1l, g_wc1l);
    cudaGetSymbolAddress((void**)&wc2h, g_wc2h);  cudaGetSymbolAddress((void**)&wc2l, g_wc2l);
    cudaGetSymbolAddress((void**)&wc3h, g_wc3h);  cudaGetSymbolAddress((void**)&wc3l, g_wc3l);
    cudaGetSymbolAddress((void**)&wd1h, g_wd1h);  cudaGetSymbolAddress((void**)&wd1l, g_wd1l);
    cudaGetSymbolAddress((void**)&wd3h, g_wd3h);  cudaGetSymbolAddress((void**)&wd3l, g_wd3l);
    cudaGetSymbolAddress((void**)&wp1th, g_wp1th); cudaGetSymbolAddress((void**)&wp1tl, g_wp1tl);
    cudaGetSymbolAddress((void**)&wp1bh, g_wp1bh); cudaGetSymbolAddress((void**)&wp1bl, g_wp1bl);
    cudaGetSymbolAddress((void**)&sHSh, g_sHSh);  cudaGetSymbolAddress((void**)&sHSl, g_sHSl);
    cudaGetSymbolAddress((void**)&GT,   g_GT);

    // prep
    split_arr<<<(N_TOT * DIM + 255) / 256, 256>>>(NEs, NEh, NEl, N_TOT * DIM);
    split_weights<<<SPLITW_BLOCKS, 256>>>(Wa, Wc0, Wc1, Wc2, Wc3, Wd1, Wd3, Wp1,
        wah, wal, wc0h, wc0l, wc1h, wc1l, wc2h, wc2l, wc3h, wc3l,
        wd1h, wd1l, wd3h, wd3l, wp1th, wp1tl, wp1bh, wp1bl);

    // 1) hats = relu(NEs @ Wa + ba) -> hi/lo
    gemm128<<<dim3(DIM / 128, N_TOT / 128), 256, G128_DYN>>>(NEh, NEl, wah, wal, ba,
        hh, hl, DIM, DIM);

    // 2) segment max + select + state_seq
    seg_reduce<<<GRP, DIM>>>(hh, hl, nodes, act, HAts, seqf, seqh, seql);

    // 3) TCN (fused Wd residual in layers 1 and 3)
    tcn64<0><<<dim3(4, 24), 128, T64_DYN>>>(seqh, seql, wc0h, wc0l, nullptr, nullptr,
        bc0, seqf, nullptr, x1h, x1l, SEQL, 256, 256, 3, 1, 1);
    tcn64<1><<<dim3(8, 24), 128, T64_DYN>>>(x1h, x1l, wc1h, wc1l, wd1h, wd1l,
        bc1, nullptr, x2f, x2h, x2l, SEQL, 512, 256, 4, 2, 1);
    tcn64<0><<<dim3(8, 24), 128, T64_DYN>>>(x2h, x2l, wc2h, wc2l, nullptr, nullptr,
        bc2, x2f, nullptr, x1h, x1l, SEQL, 512, 512, 3, 4, 1);
    tcn64<1><<<dim3(4, 24), 128, T64_DYN>>>(x1h, x1l, wc3h, wc3l, wd3h, wd3l,
        bc3, nullptr, x2f, nullptr, nullptr, SEQL, 256, 512, 4, 8, 1);

    // 4) state_HS and group term GT = sHS @ Wp1top + bp1
    build_sHS<<<GRP, DIM>>>(query, x2f, HAts, sHSh, sHSl);
    tcn64<0><<<dim3(8, 8), 128, T64_DYN>>>(sHSh, sHSl, wp1th, wp1tl, nullptr, nullptr,
        bp1, nullptr, GT, nullptr, nullptr, GRP, HID, 768, 1, 0, 0);

    // 5) fused final GEMM + Wp2 reduction
    final_mma<<<GRP, 256, FIN_DYN>>>(hh, hl, wp1bh, wp1bl, GT, Wp2, bp2, out);
}

// round 8
// speedup vs baseline: 2.8977x; 1.0729x over previous
#include <cuda_runtime.h>
#include <cuda_bf16.h>
#include <cstdint>

#define N_TOT 65536
#define GRP   512
#define PER   128
#define DIM   256
#define SEQL  1534
#define HID   512
#define KCH   32

typedef __nv_bfloat16 bf16;

// ---------------- scratch (device globals; no allocation allowed) ----------
__device__ bf16  g_NEh [N_TOT * DIM];
__device__ bf16  g_NEl [N_TOT * DIM];
__device__ bf16  g_hh  [N_TOT * DIM];
__device__ bf16  g_hl  [N_TOT * DIM];
__device__ float g_HAts[GRP * DIM];
__device__ float g_seqf[1536 * DIM];
__device__ bf16  g_seqh[1536 * DIM];
__device__ bf16  g_seql[1536 * DIM];
__device__ bf16  g_x1h [1536 * 512];
__device__ bf16  g_x1l [1536 * 512];
__device__ float g_x2f [1536 * 512];
__device__ bf16  g_x2h [1536 * 512];
__device__ bf16  g_x2l [1536 * 512];
__device__ bf16  g_wah [DIM * DIM];
__device__ bf16  g_wal [DIM * DIM];
__device__ bf16  g_wc0h[3 * 256 * 256];
__device__ bf16  g_wc0l[3 * 256 * 256];
__device__ bf16  g_wc1h[3 * 512 * 256];
__device__ bf16  g_wc1l[3 * 512 * 256];
__device__ bf16  g_wc2h[3 * 512 * 512];
__device__ bf16  g_wc2l[3 * 512 * 512];
__device__ bf16  g_wc3h[3 * 256 * 512];
__device__ bf16  g_wc3l[3 * 256 * 512];
__device__ bf16  g_wd1h[512 * 256];
__device__ bf16  g_wd1l[512 * 256];
__device__ bf16  g_wd3h[256 * 512];
__device__ bf16  g_wd3l[256 * 512];
__device__ bf16  g_wp1th[512 * 768];
__device__ bf16  g_wp1tl[512 * 768];
__device__ bf16  g_wp1bh[512 * 256];
__device__ bf16  g_wp1bl[512 * 256];
__device__ bf16  g_sHSh[GRP * 768];
__device__ bf16  g_sHSl[GRP * 768];
__device__ float g_GT  [GRP * 512];

// ---------------- low-level helpers -----------------------------------------
__device__ __forceinline__ uint32_t smem_u32(const void* p) {
    uint32_t a;
    asm("{ .reg .u64 t; cvta.to.shared.u64 t, %1; cvt.u32.u64 %0, t; }"
        : "=r"(a) : "l"(p));
    return a;
}
static __device__ __forceinline__ uint32_t SWZ(uint32_t off) {
    return off ^ ((off >> 3) & 0x70);
}
__device__ __forceinline__ void mma_bf16(float* c, const uint32_t* a, const uint32_t* b) {
    asm volatile(
        "mma.sync.aligned.m16n8k16.row.col.f32.bf16.bf16.f32 "
        "{%0,%1,%2,%3}, {%4,%5,%6,%7}, {%8,%9}, {%0,%1,%2,%3};\n"
        : "+f"(c[0]), "+f"(c[1]), "+f"(c[2]), "+f"(c[3])
        : "r"(a[0]), "r"(a[1]), "r"(a[2]), "r"(a[3]), "r"(b[0]), "r"(b[1]));
}
__device__ __forceinline__ void ldm_x4(uint32_t* r, uint32_t a) {
    asm volatile("ldmatrix.sync.aligned.m8n8.x4.shared.b16 {%0,%1,%2,%3}, [%4];"
        : "=r"(r[0]), "=r"(r[1]), "=r"(r[2]), "=r"(r[3]) : "r"(a));
}
#define CP16(dst, src, pred) do {                                              \
    int _sz = (pred) ? 16 : 0;                                                 \
    asm volatile("cp.async.cg.shared.global [%0], [%1], 16, %2;"               \
        :: "r"(dst), "l"(src), "r"(_sz) : "memory"); } while (0)
#define CP_COMMIT() asm volatile("cp.async.commit_group;" ::: "memory")
#define CP_WAIT1()  asm volatile("cp.async.wait_group 1;" ::: "memory")
#define CP_WAIT0()  asm volatile("cp.async.wait_group 0;" ::: "memory")

// ---------------- split helpers ---------------------------------------------
__device__ __forceinline__ void split2(float v, bf16& h, bf16& l) {
    h = __float2bfloat16(v);
    l = __float2bfloat16(v - __bfloat162float(h));
}
__global__ void split_arr(const float* __restrict__ x, bf16* __restrict__ h,
                          bf16* __restrict__ l, int n)
{
    int i = blockIdx.x * 256 + threadIdx.x;
    if (i < n) { bf16 a, b; split2(x[i], a, b); h[i] = a; l[i] = b; }
}
__device__ __forceinline__ void d_tsplit(const float* w, bf16* h, bf16* l,
                                         int K, int N, int i)
{
    if (i < K * N) {
        int k = i / N, n = i % N;
        bf16 a, b; split2(w[i], a, b);
        h[(size_t)n * K + k] = a;
        l[(size_t)n * K + k] = b;
    }
}
__device__ __forceinline__ void d_conv(const float* w, bf16* h, bf16* l,
                                       int Cout, int Cin, int i)
{
    if (i < Cout * Cin * 3) {
        int j  = i % 3;
        int ci = (i / 3) % Cin;
        int co = i / (3 * Cin);
        bf16 a, b; split2(w[i], a, b);
        size_t d = ((size_t)j * Cout + co) * Cin + ci;
        h[d] = a; l[d] = b;
    }
}
__device__ __forceinline__ void d_arr(const float* w, bf16* h, bf16* l, int n, int i)
{
    if (i < n) { bf16 a, b; split2(w[i], a, b); h[i] = a; l[i] = b; }
}

__global__ void split_weights(
    const float* Wa, const float* Wc0, const float* Wc1, const float* Wc2,
    const float* Wc3, const float* Wd1, const float* Wd3, const float* Wp1,
    bf16* wah, bf16* wal, bf16* wc0h, bf16* wc0l, bf16* wc1h, bf16* wc1l,
    bf16* wc2h, bf16* wc2l, bf16* wc3h, bf16* wc3l, bf16* wd1h, bf16* wd1l,
    bf16* wd3h, bf16* wd3l, bf16* wp1th, bf16* wp1tl, bf16* wp1bh, bf16* wp1bl)
{
    int b = blockIdx.x, t = threadIdx.x;
    if (b < 256)        { d_tsplit(Wa, wah, wal, 256, 256, b * 256 + t); return; }
    b -= 256;
    if (b < 768)        { d_conv(Wc0, wc0h, wc0l, 256, 256, b * 256 + t); return; }
    b -= 768;
    if (b < 1536)       { d_conv(Wc1, wc1h, wc1l, 512, 256, b * 256 + t); return; }
    b -= 1536;
    if (b < 3072)       { d_conv(Wc2, wc2h, wc2l, 512, 512, b * 256 + t); return; }
    b -= 3072;
    if (b < 1536)       { d_conv(Wc3, wc3h, wc3l, 256, 512, b * 256 + t); return; }
    b -= 1536;
    if (b < 512)        { d_arr(Wd1, wd1h, wd1l, 512 * 256, b * 256 + t); return; }
    b -= 512;
    if (b < 512)        { d_arr(Wd3, wd3h, wd3l, 256 * 512, b * 256 + t); return; }
    b -= 512;
    if (b < 1536)       { d_tsplit(Wp1, wp1th, wp1tl, 768, 512, b * 256 + t); return; }
    b -= 1536;
    if (b < 512)        { d_tsplit(Wp1 + 768 * 512, wp1bh, wp1bl, 256, 512, b * 256 + t); }
}
#define SPLITW_BLOCKS (256 + 768 + 1536 + 3072 + 1536 + 512 + 512 + 1536 + 512)

// ---------------- warp compute for one k32 chunk -----------------------------
// smem A rows are 128B ([32 hi bf16 | 32 lo bf16]); aoff = A tile row offset.
template<int NBT>
__device__ __forceinline__ void compute_chunk_t(uint32_t Ab, uint32_t Bb, int aoff,
                                                int wm, int wn, int lane,
                                                float acc[2][NBT][4])
{
    int l7 = lane & 7;
    int b3 = (lane >> 3) & 1;
    int b4 = (lane >> 4) & 1;
    #pragma unroll
    for (int ks = 0; ks < 2; ks++) {
        int colb = ks * 32;
        uint32_t bh[NBT][2], bl[NBT][2];
        #pragma unroll
        for (int pp = 0; pp < NBT / 2; pp++) {
            int nrow = wn + pp * 16 + b4 * 8 + l7;
            uint32_t off = nrow * 128 + colb + b3 * 16;
            uint32_t rh[4], rl[4];
            ldm_x4(rh, Bb + SWZ(off));
            ldm_x4(rl, Bb + SWZ(off + 64));
            bh[pp * 2 + 0][0] = rh[0]; bh[pp * 2 + 0][1] = rh[1];
            bh[pp * 2 + 1][0] = rh[2]; bh[pp * 2 + 1][1] = rh[3];
            bl[pp * 2 + 0][0] = rl[0]; bl[pp * 2 + 0][1] = rl[1];
            bl[pp * 2 + 1][0] = rl[2]; bl[pp * 2 + 1][1] = rl[3];
        }
        #pragma unroll
        for (int mt = 0; mt < 2; mt++) {
            int arow = aoff + wm + mt * 16 + b3 * 8 + l7;
            uint32_t off = arow * 128 + colb + b4 * 16;
            uint32_t ah[4], al[4];
            ldm_x4(ah, Ab + SWZ(off));
            ldm_x4(al, Ab + SWZ(off + 64));
            #pragma unroll
            for (int bt = 0; bt < NBT; bt++) {
                mma_bf16(acc[mt][bt], ah, bh[bt]);
                mma_bf16(acc[mt][bt], ah, bl[bt]);
                mma_bf16(acc[mt][bt], al, bh[bt]);
            }
        }
    }
}

// ---------------- hats GEMM: 128x128 tiles, 256 threads ----------------------
#define G128_STAGE 32768u
#define G128_DYN   (2 * 32768 + 1024)
__global__ __launch_bounds__(256, 2)
void gemm128(const bf16* __restrict__ Agh, const bf16* __restrict__ Agl,
             const bf16* __restrict__ Wgh, const bf16* __restrict__ Wgl,
             const float* __restrict__ bias,
             bf16* __restrict__ Ch, bf16* __restrict__ Cl, int N, int K)
{
    extern __shared__ char dyn[];
    uint32_t sbase = (smem_u32(dyn) + 1023u) & ~1023u;
    int tid = threadIdx.x, lane = tid & 31, w = tid >> 5;
    int wm = (w & 3) * 32, wn = (w >> 2) * 64;
    int row0 = blockIdx.y * 128, col0 = blockIdx.x * 128;
    int nch = K / KCH;

    auto load_stage = [&](int c, int s) {
        int k0 = c * KCH;
        uint32_t Ab = sbase + (uint32_t)s * G128_STAGE;
        uint32_t Bb = Ab + 16384u;
        #pragma unroll
        for (int t = 0; t < 4; t++) {
            int idx = tid + t * 256;
            int row = idx >> 3, sub = idx & 7, half = sub >> 2, q = sub & 3;
            const bf16* src = (half ? Agl : Agh) + (size_t)(row0 + row) * K + k0 + q * 8;
            CP16(Ab + SWZ(row * 128 + half * 64 + q * 16), src, 1);
        }
        #pragma unroll
        for (int t = 0; t < 4; t++) {
            int idx = tid + t * 256;
            int row = idx >> 3, sub = idx & 7, half = sub >> 2, q = sub & 3;
            const bf16* src = (half ? Wgl : Wgh) + (size_t)(col0 + row) * K + k0 + q * 8;
            CP16(Bb + SWZ(row * 128 + half * 64 + q * 16), src, 1);
        }
    };

    float acc[2][8][4] = {};
    load_stage(0, 0); CP_COMMIT();
    load_stage(1, 1); CP_COMMIT();
    for (int c = 0; c < nch; c++) {
        if (c + 1 < nch) { CP_WAIT1(); } else { CP_WAIT0(); }
        __syncthreads();
        uint32_t Ab = sbase + (uint32_t)(c & 1) * G128_STAGE;
        compute_chunk_t<8>(Ab, Ab + 16384u, 0, wm, wn, lane, acc);
        __syncthreads();
        if (c + 2 < nch) { load_stage(c + 2, c & 1); CP_COMMIT(); }
    }

    #pragma unroll
    for (int mt = 0; mt < 2; mt++) {
        #pragma unroll
        for (int ih = 0; ih < 2; ih++) {
            int rr = row0 + wm + mt * 16 + ih * 8 + (lane >> 2);
            #pragma unroll
            for (int bt = 0; bt < 8; bt++) {
                int cc = col0 + wn + bt * 8 + (lane & 3) * 2;
                float v0 = fmaxf(acc[mt][bt][ih * 2 + 0] + bias[cc], 0.f);
                float v1 = fmaxf(acc[mt][bt][ih * 2 + 1] + bias[cc + 1], 0.f);
                size_t idx = (size_t)rr * N + cc;
                bf16 h0, l0, h1, l1;
                split2(v0, h0, l0); split2(v1, h1, l1);
                __nv_bfloat162 hp = {h0, h1}, lp = {l0, l1};
                *(__nv_bfloat162*)(Ch + idx) = hp;
                *(__nv_bfloat162*)(Cl + idx) = lp;
            }
        }
    }
}

// ---------------- TCN with halo: load A once, compute all taps ---------------
// A tile: (64 + 2*dil) rows with halo; tap p reads at row offset p*dil
// (Wd pass reads at 2*dil, same as tap 2). One chunk = one A load + npass B
// tiles + npass compute passes. grid (N/64, 24), 128 threads.
#define TH_AROWS  80
#define TH_ABYTES (TH_AROWS * 128)           // 10240
#define TH_STAGE  (TH_ABYTES + 4 * 8192)     // 43008 (max: 4 B tiles)
#define TH_DYN    (2 * TH_STAGE + 1024)
template<int DUAL>
__global__ __launch_bounds__(128, 2)
void tcn64(const bf16* __restrict__ Agh, const bf16* __restrict__ Agl,
           const bf16* __restrict__ Wgh, const bf16* __restrict__ Wgl,
           const bf16* __restrict__ Wdh, const bf16* __restrict__ Wdl,
           const float* __restrict__ bias, const float* __restrict__ Rf,
           float* __restrict__ Cf, bf16* __restrict__ Ch, bf16* __restrict__ Cl,
           int Mv, int N, int K, int npass, int dil, int doRelu)
{
    extern __shared__ char dyn[];
    uint32_t sbase = (smem_u32(dyn) + 1023u) & ~1023u;
    int tid = threadIdx.x, lane = tid & 31, w = tid >> 5;
    int wm = (w & 1) * 32, wn = (w >> 1) * 32;
    int row0 = blockIdx.y * 64, col0 = blockIdx.x * 64;
    int halo = (npass >= 3) ? 2 * dil : 0;
    int nrows = 64 + halo;
    int nch = K / KCH;

    auto load_stage = [&](int c, int s) {
        int k0 = c * KCH;
        uint32_t Ab = sbase + (uint32_t)s * TH_STAGE;
        for (int idx = tid; idx < nrows * 8; idx += 128) {
            int row = idx >> 3, sub = idx & 7, half = sub >> 2, q = sub & 3;
            int ga = row0 - halo + row;
            const bf16* src = (half ? Agl : Agh)
                              + (size_t)(ga < 0 ? 0 : ga) * K + k0 + q * 8;
            CP16(Ab + SWZ(row * 128 + half * 64 + q * 16), src, ga >= 0);
        }
        for (int p = 0; p < npass; p++) {
            const bf16* Ph = (p < 3) ? Wgh + (size_t)p * N * K : Wdh;
            const bf16* Pl = (p < 3) ? Wgl + (size_t)p * N * K : Wdl;
            uint32_t Bb = Ab + TH_ABYTES + (uint32_t)p * 8192u;
            #pragma unroll
            for (int t = 0; t < 4; t++) {
                int idx = tid + t * 128;
                int row = idx >> 3, sub = idx & 7, half = sub >> 2, q = sub & 3;
                const bf16* src = (half ? Pl : Ph) + (size_t)(col0 + row) * K + k0 + q * 8;
                CP16(Bb + SWZ(row * 128 + half * 64 + q * 16), src, 1);
            }
        }
    };

    float acc[2][4][4] = {};
    float accR[DUAL ? 2 : 1][DUAL ? 4 : 1][DUAL ? 4 : 1] = {};
    load_stage(0, 0); CP_COMMIT();
    if (nch > 1) { load_stage(1, 1); CP_COMMIT(); }
    for (int c = 0; c < nch; c++) {
        if (c + 1 < nch) { CP_WAIT1(); } else { CP_WAIT0(); }
        __syncthreads();
        uint32_t Ab = sbase + (uint32_t)(c & 1) * TH_STAGE;
        for (int p = 0; p < npass; p++) {
            int aoff = (p < 3) ? p * dil : 2 * dil;
            uint32_t Bb = Ab + TH_ABYTES + (uint32_t)p * 8192u;
            if (DUAL && p == 3)
                compute_chunk_t<4>(Ab, Bb, aoff, wm, wn, lane, (float (*)[4][4])accR);
            else
                compute_chunk_t<4>(Ab, Bb, aoff, wm, wn, lane, acc);
        }
        __syncthreads();
        if (c + 2 < nch) { load_stage(c + 2, c & 1); CP_COMMIT(); }
    }

    #pragma unroll
    for (int mt = 0; mt < 2; mt++) {
        #pragma unroll
        for (int ih = 0; ih < 2; ih++) {
            int rr = row0 + wm + mt * 16 + ih * 8 + (lane >> 2);
            if (rr >= Mv) continue;
            #pragma unroll
            for (int bt = 0; bt < 4; bt++) {
                int cc = col0 + wn + bt * 8 + (lane & 3) * 2;
                size_t idx = (size_t)rr * N + cc;
                float v0 = acc[mt][bt][ih * 2 + 0] + bias[cc];
                float v1 = acc[mt][bt][ih * 2 + 1] + bias[cc + 1];
                if (doRelu) { v0 = fmaxf(v0, 0.f); v1 = fmaxf(v1, 0.f); }
                if (DUAL) {
                    v0 = fmaxf(v0 + accR[mt][bt][ih * 2 + 0], 0.f);
                    v1 = fmaxf(v1 + accR[mt][bt][ih * 2 + 1], 0.f);
                } else if (Rf) {
                    float2 rv = *(const float2*)(Rf + idx);
                    v0 = fmaxf(v0 + rv.x, 0.f);
                    v1 = fmaxf(v1 + rv.y, 0.f);
                }
                if (Cf) *(float2*)(Cf + idx) = make_float2(v0, v1);
                if (Ch) {
                    bf16 h0, l0, h1, l1;
                    split2(v0, h0, l0); split2(v1, h1, l1);
                    __nv_bfloat162 hp = {h0, h1}, lp = {l0, l1};
                    *(__nv_bfloat162*)(Ch + idx) = hp;
                    *(__nv_bfloat162*)(Cl + idx) = lp;
                }
            }
        }
    }
}

// ---------------- fused final: out = relu(hats@Wp1bot + GT[g]) @ Wp2 + bp2 --
#define FIN_STAGE 24576u
#define FIN_DYN   (2 * 24576 + 1024)
__global__ __launch_bounds__(256, 2)
void final_mma(const bf16* __restrict__ Hh, const bf16* __restrict__ Hl,
               const bf16* __restrict__ Bgh, const bf16* __restrict__ Bgl,
               const float* __restrict__ GT, const float* __restrict__ W2,
               const float* __restrict__ bp2, float* __restrict__ out)
{
    extern __shared__ char dyn[];
    __shared__ float sGT[512], sW2[512], sred[128][2];
    uint32_t sbase = (smem_u32(dyn) + 1023u) & ~1023u;
    int g = blockIdx.x;
    int tid = threadIdx.x, lane = tid & 31, w = tid >> 5;
    int wm = (w & 3) * 32, wn = (w >> 2) * 32;

    for (int i = tid; i < 512; i += 256) {
        sGT[i] = GT[(size_t)g * 512 + i];
        sW2[i] = W2[i];
    }

    const bf16* Ah = Hh + (size_t)g * PER * DIM;
    const bf16* Al = Hl + (size_t)g * PER * DIM;

    auto load_stage = [&](int c, int s) {
        int nt = c >> 3;
        int k0 = (c & 7) * KCH;
        uint32_t Ab = sbase + (uint32_t)s * FIN_STAGE;
        uint32_t Bb = Ab + 16384u;
        #pragma unroll
        for (int t = 0; t < 4; t++) {
            int idx = tid + t * 256;
            int row = idx >> 3, sub = idx & 7, half = sub >> 2, q = sub & 3;
            const bf16* src = (half ? Al : Ah) + (size_t)row * DIM + k0 + q * 8;
            CP16(Ab + SWZ(row * 128 + half * 64 + q * 16), src, 1);
        }
        #pragma unroll
        for (int t = 0; t < 2; t++) {
            int idx = tid + t * 256;
            int row = idx >> 3, sub = idx & 7, half = sub >> 2, q = sub & 3;
            const bf16* src = (half ? Bgl : Bgh)
                              + (size_t)(nt * 64 + row) * DIM + k0 + q * 8;
            CP16(Bb + SWZ(row * 128 + half * 64 + q * 16), src, 1);
        }
    };

    float acc[2][4][4] = {};
    float qsum[4] = {};
    const int nch = 64;
    load_stage(0, 0); CP_COMMIT();
    load_stage(1, 1); CP_COMMIT();
    for (int c = 0; c < nch; c++) {
        if (c + 1 < nch) { CP_WAIT1(); } else { CP_WAIT0(); }
        __syncthreads();
        uint32_t Ab = sbase + (uint32_t)(c & 1) * FIN_STAGE;
        compute_chunk_t<4>(Ab, Ab + 16384u, 0, wm, wn, lane, acc);
        __syncthreads();
        if (c + 2 < nch) { load_stage(c + 2, c & 1); CP_COMMIT(); }
        if ((c & 7) == 7) {
            int nt = c >> 3;
            #pragma unroll
            for (int mt = 0; mt < 2; mt++) {
                #pragma unroll
                for (int bt = 0; bt < 4; bt++) {
                    #pragma unroll
                    for (int i = 0; i < 4; i++) {
                        int cc = nt * 64 + wn + bt * 8 + (lane & 3) * 2 + (i & 1);
                        float hv = fmaxf(acc[mt][bt][i] + sGT[cc], 0.f);
                        qsum[mt * 2 + (i >> 1)] += hv * sW2[cc];
                        acc[mt][bt][i] = 0.f;
                    }
                }
            }
        }
    }

    #pragma unroll
    for (int mt = 0; mt < 2; mt++) {
        #pragma unroll
        for (int ih = 0; ih < 2; ih++) {
            float v = qsum[mt * 2 + ih];
            v += __shfl_xor_sync(0xffffffffu, v, 1);
            v += __shfl_xor_sync(0xffffffffu, v, 2);
            if ((lane & 3) == 0)
                sred[wm + mt * 16 + ih * 8 + (lane >> 2)][w >> 2] = v;
        }
    }
    __syncthreads();
    if (tid < 128)
        out[(size_t)g * PER + tid] = sred[tid][0] + sred[tid][1] + bp2[0];
}

// ---------------- per-group max + state_seq build (vectorized) ---------------
__global__ void seg_reduce(const bf16* __restrict__ hh, const bf16* __restrict__ hl,
                           const float* __restrict__ nodes, const int* __restrict__ act,
                           float* __restrict__ HAts, float* __restrict__ seqf,
                           bf16* __restrict__ seqh, bf16* __restrict__ seql)
{
    __shared__ float2 sm[2][128];
    int g = blockIdx.x, tid = threadIdx.x;
    int c2 = tid & 127, hf = tid >> 7;
    const __nv_bfloat162* bh = (const __nv_bfloat162*)(hh + (size_t)g * PER * DIM) + c2;
    const __nv_bfloat162* bl = (const __nv_bfloat162*)(hl + (size_t)g * PER * DIM) + c2;
    float2 m = make_float2(-3.4e38f, -3.4e38f);
    #pragma unroll 4
    for (int r = hf * 64; r < hf * 64 + 64; r++) {
        __nv_bfloat162 a = bh[(size_t)r * 128];
        __nv_bfloat162 b = bl[(size_t)r * 128];
        m.x = fmaxf(m.x, __bfloat162float(a.x) + __bfloat162float(b.x));
        m.y = fmaxf(m.y, __bfloat162float(a.y) + __bfloat162float(b.y));
    }
    sm[hf][c2] = m;
    __syncthreads();
    if (hf) return;
    float2 o = sm[1][c2];
    m.x = fmaxf(m.x, o.x);
    m.y = fmaxf(m.y, o.y);
    int c = 2 * c2;
    HAts[g * DIM + c]     = m.x;
    HAts[g * DIM + c + 1] = m.y;
    auto wr = [&](int row, float v0, float v1) {
        size_t id = (size_t)row * DIM + c;
        seqf[id] = v0; seqf[id + 1] = v1;
        bf16 h0, l0, h1, l1;
        split2(v0, h0, l0); split2(v1, h1, l1);
        __nv_bfloat162 hp = {h0, h1}, lp = {l0, l1};
        *(__nv_bfloat162*)(seqh + id) = hp;
        *(__nv_bfloat162*)(seql + id) = lp;
    };
    if (g < GRP - 1) {
        wr(3 * g + 0, nodes[g * DIM + c], nodes[g * DIM + c + 1]);
        wr(3 * g + 1, m.x, m.y);
        int a = act[g];
        __nv_bfloat162 sh = bh[(size_t)a * 128];
        __nv_bfloat162 sl = bl[(size_t)a * 128];
        wr(3 * g + 2, __bfloat162float(sh.x) + __bfloat162float(sl.x),
                      __bfloat162float(sh.y) + __bfloat162float(sl.y));
    } else {
        wr(SEQL - 1, nodes[(GRP - 1) * DIM + c], nodes[(GRP - 1) * DIM + c + 1]);
    }
}

// ---------------- build state_HS = [query | hs | HAts] (hi/lo) --------------
__global__ void build_sHS(const float* __restrict__ query, const float* __restrict__ xf,
                          const float* __restrict__ HAts, bf16* __restrict__ h,
                          bf16* __restrict__ l)
{
    int g = blockIdx.x, c = threadIdx.x;
    bf16 a, b;
    split2(query[g * DIM + c], a, b);
    h[g * 768 + c] = a; l[g * 768 + c] = b;
    split2(xf[(size_t)(3 * g) * DIM + c], a, b);
    h[g * 768 + 256 + c] = a; l[g * 768 + 256 + c] = b;
    split2(HAts[g * DIM + c], a, b);
    h[g * 768 + 512 + c] = a; l[g * 768 + 512 + c] = b;
}

// ---------------- launcher --------------------------------------------------
extern "C" void kernel_launch(void* const* d_in, const int* in_sizes, int n_in,
                              void* d_out, int out_size)
{
    const float* NEs   = (const float*)d_in[0];
    const float* nodes = (const float*)d_in[1];
    const float* query = (const float*)d_in[2];
    const int*   act   = (const int*)d_in[4];
    const float* Wa    = (const float*)d_in[5];
    const float* ba    = (const float*)d_in[6];
    const float* Wc0   = (const float*)d_in[7];
    const float* bc0   = (const float*)d_in[8];
    const float* Wc1   = (const float*)d_in[9];
    const float* bc1   = (const float*)d_in[10];
    const float* Wd1   = (const float*)d_in[11];
    const float* Wc2   = (const float*)d_in[12];
    const float* bc2   = (const float*)d_in[13];
    const float* Wc3   = (const float*)d_in[14];
    const float* bc3   = (const float*)d_in[15];
    const float* Wd3   = (const float*)d_in[16];
    const float* Wp1   = (const float*)d_in[17];
    const float* bp1   = (const float*)d_in[18];
    const float* Wp2   = (const float*)d_in[19];
    const float* bp2   = (const float*)d_in[20];
    float* out = (float*)d_out;

    cudaFuncSetAttribute(gemm128,  cudaFuncAttributeMaxDynamicSharedMemorySize, G128_DYN);
    cudaFuncSetAttribute(tcn64<0>, cudaFuncAttributeMaxDynamicSharedMemorySize, TH_DYN);
    cudaFuncSetAttribute(tcn64<1>, cudaFuncAttributeMaxDynamicSharedMemorySize, TH_DYN);
    cudaFuncSetAttribute(final_mma, cudaFuncAttributeMaxDynamicSharedMemorySize, FIN_DYN);

    bf16 *NEh, *NEl, *hh, *hl, *seqh, *seql, *x1h, *x1l, *x2h, *x2l;
    bf16 *wah, *wal, *wc0h, *wc0l, *wc1h, *wc1l, *wc2h, *wc2l, *wc3h, *wc3l;
    bf16 *wd1h, *wd1l, *wd3h, *wd3l, *wp1th, *wp1tl, *wp1bh, *wp1bl, *sHSh, *sHSl;
    float *HAts, *seqf, *x2f, *GT;
    cudaGetSymbolAddress((void**)&NEh,  g_NEh);   cudaGetSymbolAddress((void**)&NEl,  g_NEl);
    cudaGetSymbolAddress((void**)&hh,   g_hh);    cudaGetSymbolAddress((void**)&hl,   g_hl);
    cudaGetSymbolAddress((void**)&HAts, g_HAts);
    cudaGetSymbolAddress((void**)&seqf, g_seqf);
    cudaGetSymbolAddress((void**)&seqh, g_seqh);  cudaGetSymbolAddress((void**)&seql, g_seql);
    cudaGetSymbolAddress((void**)&x1h,  g_x1h);   cudaGetSymbolAddress((void**)&x1l,  g_x1l);
    cudaGetSymbolAddress((void**)&x2f,  g_x2f);
    cudaGetSymbolAddress((void**)&x2h,  g_x2h);   cudaGetSymbolAddress((void**)&x2l,  g_x2l);
    cudaGetSymbolAddress((void**)&wah,  g_wah);   cudaGetSymbolAddress((void**)&wal,  g_wal);
    cudaGetSymbolAddress((void**)&wc0h, g_wc0h);  cudaGetSymbolAddress((void**)&wc0l, g_wc0l);
    cudaGetSymbolAddress((void**)&wc1h, g_wc1h);  cudaGetSymbolAddress((void**)&wc1l, g_wc1l);
    cudaGetSymbolAddress((void**)&wc2h, g_wc2h);  cudaGetSymbolAddress((void**)&wc2l, g_wc2l);
    cudaGetSymbolAddress((void**)&wc3h, g_wc3h);  cudaGetSymbolAddress((void**)&wc3l, g_wc3l);
    cudaGetSymbolAddress((void**)&wd1h, g_wd1h);  cudaGetSymbolAddress((void**)&wd1l, g_wd1l);
    cudaGetSymbolAddress((void**)&wd3h, g_wd3h);  cudaGetSymbolAddress((void**)&wd3l, g_wd3l);
    cudaGetSymbolAddress((void**)&wp1th, g_wp1th); cudaGetSymbolAddress((void**)&wp1tl, g_wp1tl);
    cudaGetSymbolAddress((void**)&wp1bh, g_wp1bh); cudaGetSymbolAddress((void**)&wp1bl, g_wp1bl);
    cudaGetSymbolAddress((void**)&sHSh, g_sHSh);  cudaGetSymbolAddress((void**)&sHSl, g_sHSl);
    cudaGetSymbolAddress((void**)&GT,   g_GT);

    // prep (launches 0-1)
    split_arr<<<(N_TOT * DIM + 255) / 256, 256>>>(NEs, NEh, NEl, N_TOT * DIM);
    split_weights<<<SPLITW_BLOCKS, 256>>>(Wa, Wc0, Wc1, Wc2, Wc3, Wd1, Wd3, Wp1,
        wah, wal, wc0h, wc0l, wc1h, wc1l, wc2h, wc2l, wc3h, wc3l,
        wd1h, wd1l, wd3h, wd3l, wp1th, wp1tl, wp1bh, wp1bl);

    // 1) hats (launch 2)
    gemm128<<<dim3(DIM / 128, N_TOT / 128), 256, G128_DYN>>>(NEh, NEl, wah, wal, ba,
        hh, hl, DIM, DIM);

    // 2) segment max + select + state_seq (launch 3)
    seg_reduce<<<GRP, 256>>>(hh, hl, nodes, act, HAts, seqf, seqh, seql);

    // 3) TCN halo kernels (launches 4-7; launch 5 = DUAL layer 1 is profiled)
    tcn64<0><<<dim3(4, 24), 128, TH_DYN>>>(seqh, seql, wc0h, wc0l, nullptr, nullptr,
        bc0, seqf, nullptr, x1h, x1l, SEQL, 256, 256, 3, 1, 1);
    tcn64<1><<<dim3(8, 24), 128, TH_DYN>>>(x1h, x1l, wc1h, wc1l, wd1h, wd1l,
        bc1, nullptr, x2f, x2h, x2l, SEQL, 512, 256, 4, 2, 1);
    tcn64<0><<<dim3(8, 24), 128, TH_DYN>>>(x2h, x2l, wc2h, wc2l, nullptr, nullptr,
        bc2, x2f, nullptr, x1h, x1l, SEQL, 512, 512, 3, 4, 1);
    tcn64<1><<<dim3(4, 24), 128, TH_DYN>>>(x1h, x1l, wc3h, wc3l, wd3h, wd3l,
        bc3, nullptr, x2f, nullptr, nullptr, SEQL, 256, 512, 4, 8, 1);

    // 4) state_HS and group term GT = sHS @ Wp1top + bp1
    build_sHS<<<GRP, DIM>>>(query, x2f, HAts, sHSh, sHSl);
    tcn64<0><<<dim3(8, 8), 128, TH_DYN>>>(sHSh, sHSl, wp1th, wp1tl, nullptr, nullptr,
        bp1, nullptr, GT, nullptr, nullptr, GRP, HID, 768, 1, 0, 0);

    // 5) fused final GEMM + Wp2 reduction
    final_mma<<<GRP, 256, FIN_DYN>>>(hh, hl, wp1bh, wp1bl, GT, Wp2, bp2, out);
}